// round 2
// baseline (speedup 1.0000x reference)
#include <cuda_runtime.h>
#include <cuda_bf16.h>

// Problem constants
#define BB 2
#define TT 2048
#define DD 1024
#define HH 16
#define DHH 64
#define FF 4096
#define MROWS (BB*TT)   // 4096

// ---------------------------------------------------------------------------
// Scratch (device globals; no allocations allowed)
// ---------------------------------------------------------------------------
__device__ float g_packedW[DD * 3 * DD];       // [1024][3072]
__device__ float g_qkv[MROWS * 3 * DD];        // [4096][3072]
__device__ float g_obuf[MROWS * DD];           // attention output, head-concat
__device__ float g_t1[MROWS * DD];             // attn_out, later f
__device__ float g_abuf[MROWS * DD];           // a = x + LN(attn_out)
__device__ float g_h1[MROWS * FF];             // relu(a@W1+b1)

// ---------------------------------------------------------------------------
// Repack Wq/Wk/Wv (H,D,DH) -> packed [D][3*D] with col n = w*1024 + h*64 + e
// ---------------------------------------------------------------------------
__global__ __launch_bounds__(256) void repack_kernel(
    const float* __restrict__ Wq, const float* __restrict__ Wk,
    const float* __restrict__ Wv, float* __restrict__ packed)
{
    int idx = blockIdx.x * 256 + threadIdx.x;      // 0 .. 1024*3072-1
    int d = idx / 3072;
    int n = idx - d * 3072;
    int w = n >> 10;
    int r = n & 1023;
    int h = r >> 6;
    int e = r & 63;
    const float* src = (w == 0) ? Wq : (w == 1) ? Wk : Wv;
    packed[idx] = src[h * (DD * DHH) + d * DHH + e];
}

// ---------------------------------------------------------------------------
// SGEMM: C[M,N] = A[M,K] * B[K,N] (+bias) (+relu), tiles 128x128x8,
// 256 threads, 8x8 per-thread microtile. M,N divisible by 128, K by 8.
// ---------------------------------------------------------------------------
__global__ __launch_bounds__(256) void sgemm_kernel(
    const float* __restrict__ A, int lda,
    const float* __restrict__ B, int ldb,
    float* __restrict__ C, int ldc,
    int K, const float* __restrict__ bias, int do_relu)
{
    __shared__ __align__(16) float As[8 * 132];  // As[k][m], padded
    __shared__ __align__(16) float Bs[8 * 132];  // Bs[k][n], padded

    const int tid = threadIdx.x;
    const int tx = tid & 15;
    const int ty = tid >> 4;
    const int rowBase = blockIdx.y * 128;
    const int colBase = blockIdx.x * 128;

    const int ar = tid >> 3;     // 0..31
    const int ac = tid & 7;      // 0..7
    const int br = tid >> 7;     // 0..1
    const int bc = tid & 127;    // 0..127

    const float* Aptr = A + (long)(rowBase + ar) * lda + ac;
    const float* Bptr = B + (long)br * ldb + colBase + bc;

    float acc[8][8];
    #pragma unroll
    for (int i = 0; i < 8; i++)
        #pragma unroll
        for (int j = 0; j < 8; j++) acc[i][j] = 0.f;

    for (int k0 = 0; k0 < K; k0 += 8) {
        #pragma unroll
        for (int it = 0; it < 4; it++)
            As[ac * 132 + ar + it * 32] = Aptr[(long)(it * 32) * lda + k0];
        #pragma unroll
        for (int it = 0; it < 4; it++)
            Bs[(br + it * 2) * 132 + bc] = Bptr[(long)(k0 + it * 2) * ldb];
        __syncthreads();

        #pragma unroll
        for (int k = 0; k < 8; k++) {
            float4 a0 = *(const float4*)&As[k * 132 + ty * 4];
            float4 a1 = *(const float4*)&As[k * 132 + 64 + ty * 4];
            float4 b0 = *(const float4*)&Bs[k * 132 + tx * 4];
            float4 b1 = *(const float4*)&Bs[k * 132 + 64 + tx * 4];
            float a[8] = {a0.x, a0.y, a0.z, a0.w, a1.x, a1.y, a1.z, a1.w};
            float b[8] = {b0.x, b0.y, b0.z, b0.w, b1.x, b1.y, b1.z, b1.w};
            #pragma unroll
            for (int i = 0; i < 8; i++)
                #pragma unroll
                for (int j = 0; j < 8; j++)
                    acc[i][j] += a[i] * b[j];
        }
        __syncthreads();
    }

    #pragma unroll
    for (int ih = 0; ih < 2; ih++) {
        #pragma unroll
        for (int i = 0; i < 4; i++) {
            int r = rowBase + ih * 64 + ty * 4 + i;
            #pragma unroll
            for (int jh = 0; jh < 2; jh++) {
                int c = colBase + jh * 64 + tx * 4;
                float4 v;
                v.x = acc[ih * 4 + i][jh * 4 + 0];
                v.y = acc[ih * 4 + i][jh * 4 + 1];
                v.z = acc[ih * 4 + i][jh * 4 + 2];
                v.w = acc[ih * 4 + i][jh * 4 + 3];
                if (bias) {
                    v.x += bias[c + 0]; v.y += bias[c + 1];
                    v.z += bias[c + 2]; v.w += bias[c + 3];
                }
                if (do_relu) {
                    v.x = fmaxf(v.x, 0.f); v.y = fmaxf(v.y, 0.f);
                    v.z = fmaxf(v.z, 0.f); v.w = fmaxf(v.w, 0.f);
                }
                *(float4*)&C[(long)r * ldc + c] = v;
            }
        }
    }
}

// ---------------------------------------------------------------------------
// Causal flash attention. One block per (q-tile 64 rows, head, batch).
// 256 threads, 4x4 microtiles over a 64x64 S tile, online softmax.
// qkv row layout: [row][w*1024 + h*64 + e], row = b*T + t.
// ---------------------------------------------------------------------------
__global__ __launch_bounds__(256) void attn_kernel(
    const float* __restrict__ qkv, float* __restrict__ o)
{
    extern __shared__ float sm[];
    float* Qt = sm;                 // [64][65]  Qt[k][row]
    float* Kt = Qt + 64 * 65;       // [64][65]  Kt[k][col]
    float* Ps = Kt + 64 * 65;       // [64][65]  Ps[col][row]
    float* Vs = Ps + 64 * 65;       // [64][68]  Vs[j][d]

    const int tid = threadIdx.x;
    const int tx = tid & 15;
    const int ty = tid >> 4;
    const int iq = (int)gridDim.x - 1 - (int)blockIdx.x;  // heavy tiles first
    const int h = blockIdx.y;
    const int b = blockIdx.z;
    const int rowbase_g = iq * 64;
    const long base = (long)b * TT * 3072;

    // Load Q tile, transposed into smem
    {
        int r = tid >> 2;
        int dg = (tid & 3) * 16;
        const float* qp = qkv + base + (long)(rowbase_g + r) * 3072 + h * 64 + dg;
        #pragma unroll
        for (int it = 0; it < 4; it++) {
            float4 v = *(const float4*)(qp + it * 4);
            int d = dg + it * 4;
            Qt[(d + 0) * 65 + r] = v.x;
            Qt[(d + 1) * 65 + r] = v.y;
            Qt[(d + 2) * 65 + r] = v.z;
            Qt[(d + 3) * 65 + r] = v.w;
        }
    }

    float m[4], l[4], acc[4][4];
    #pragma unroll
    for (int i = 0; i < 4; i++) {
        m[i] = -1e30f; l[i] = 0.f;
        #pragma unroll
        for (int j = 0; j < 4; j++) acc[i][j] = 0.f;
    }
    const float scale = 0.125f;  // 64^-0.5

    for (int jt = 0; jt <= iq; jt++) {
        __syncthreads();   // protect K/V/Ps vs previous iteration readers
        {
            int r = tid >> 2;
            int dg = (tid & 3) * 16;
            const float* kp = qkv + base + (long)(jt * 64 + r) * 3072 + 1024 + h * 64 + dg;
            const float* vp = kp + 1024;
            #pragma unroll
            for (int it = 0; it < 4; it++) {
                float4 kv = *(const float4*)(kp + it * 4);
                int d = dg + it * 4;
                Kt[(d + 0) * 65 + r] = kv.x;
                Kt[(d + 1) * 65 + r] = kv.y;
                Kt[(d + 2) * 65 + r] = kv.z;
                Kt[(d + 3) * 65 + r] = kv.w;
                float4 vv = *(const float4*)(vp + it * 4);
                *(float4*)&Vs[r * 68 + d] = vv;
            }
        }
        __syncthreads();

        // S = Q K^T (64x64x64)
        float s[4][4];
        #pragma unroll
        for (int i = 0; i < 4; i++)
            #pragma unroll
            for (int j = 0; j < 4; j++) s[i][j] = 0.f;

        #pragma unroll 8
        for (int k = 0; k < 64; k++) {
            float qr[4], kc[4];
            #pragma unroll
            for (int i = 0; i < 4; i++) qr[i] = Qt[k * 65 + ty * 4 + i];
            #pragma unroll
            for (int j = 0; j < 4; j++) kc[j] = Kt[k * 65 + tx * 4 + j];
            #pragma unroll
            for (int i = 0; i < 4; i++)
                #pragma unroll
                for (int j = 0; j < 4; j++)
                    s[i][j] += qr[i] * kc[j];
        }

        // mask + scale + online softmax update; write P (transposed) to smem
        #pragma unroll
        for (int i = 0; i < 4; i++) {
            int rg = rowbase_g + ty * 4 + i;
            float sv[4];
            float lm = -1e30f;
            #pragma unroll
            for (int j = 0; j < 4; j++) {
                int cg = jt * 64 + tx * 4 + j;
                sv[j] = (cg <= rg) ? s[i][j] * scale : -1e30f;
                lm = fmaxf(lm, sv[j]);
            }
            #pragma unroll
            for (int off = 8; off >= 1; off >>= 1)
                lm = fmaxf(lm, __shfl_xor_sync(0xffffffffu, lm, off));
            float mn = fmaxf(m[i], lm);
            float corr = __expf(m[i] - mn);
            float rs = 0.f;
            #pragma unroll
            for (int j = 0; j < 4; j++) {
                float p = __expf(sv[j] - mn);
                Ps[(tx * 4 + j) * 65 + ty * 4 + i] = p;
                rs += p;
            }
            #pragma unroll
            for (int off = 8; off >= 1; off >>= 1)
                rs += __shfl_xor_sync(0xffffffffu, rs, off);
            l[i] = l[i] * corr + rs;
            m[i] = mn;
            #pragma unroll
            for (int j = 0; j < 4; j++) acc[i][j] *= corr;
        }
        __syncthreads();

        // O += P V (64x64x64)
        #pragma unroll 4
        for (int k = 0; k < 64; k++) {
            float pr[4];
            #pragma unroll
            for (int i = 0; i < 4; i++) pr[i] = Ps[k * 65 + ty * 4 + i];
            float4 vv = *(const float4*)&Vs[k * 68 + tx * 4];
            #pragma unroll
            for (int i = 0; i < 4; i++) {
                acc[i][0] += pr[i] * vv.x;
                acc[i][1] += pr[i] * vv.y;
                acc[i][2] += pr[i] * vv.z;
                acc[i][3] += pr[i] * vv.w;
            }
        }
    }

    // write O / l  into [B,T,H*DH]
    #pragma unroll
    for (int i = 0; i < 4; i++) {
        float inv = 1.f / l[i];
        int rg = rowbase_g + ty * 4 + i;
        float4 v;
        v.x = acc[i][0] * inv;
        v.y = acc[i][1] * inv;
        v.z = acc[i][2] * inv;
        v.w = acc[i][3] * inv;
        *(float4*)&o[((long)(b * TT + rg)) * DD + h * 64 + tx * 4] = v;
    }
}

// ---------------------------------------------------------------------------
// out = x + LayerNorm(y)*g + be ; one block per row of 1024, 256 threads.
// ---------------------------------------------------------------------------
__global__ __launch_bounds__(256) void ln_kernel(
    const float* __restrict__ x, const float* __restrict__ y,
    const float* __restrict__ g, const float* __restrict__ be,
    float* __restrict__ out)
{
    int row = blockIdx.x;
    int tid = threadIdx.x;
    float4 v = ((const float4*)(y + (long)row * DD))[tid];
    float s  = v.x + v.y + v.z + v.w;
    float ss = v.x * v.x + v.y * v.y + v.z * v.z + v.w * v.w;
    #pragma unroll
    for (int off = 16; off >= 1; off >>= 1) {
        s  += __shfl_xor_sync(0xffffffffu, s,  off);
        ss += __shfl_xor_sync(0xffffffffu, ss, off);
    }
    __shared__ float sb[8], ssb[8];
    if ((tid & 31) == 0) { sb[tid >> 5] = s; ssb[tid >> 5] = ss; }
    __syncthreads();
    float tot = 0.f, tots = 0.f;
    #pragma unroll
    for (int w = 0; w < 8; w++) { tot += sb[w]; tots += ssb[w]; }
    float mu = tot * (1.f / 1024.f);
    float var = tots * (1.f / 1024.f) - mu * mu;
    float rstd = rsqrtf(var + 1e-5f);

    float4 xv = ((const float4*)(x + (long)row * DD))[tid];
    float4 gv = ((const float4*)g)[tid];
    float4 bv = ((const float4*)be)[tid];
    float4 o;
    o.x = xv.x + (v.x - mu) * rstd * gv.x + bv.x;
    o.y = xv.y + (v.y - mu) * rstd * gv.y + bv.y;
    o.z = xv.z + (v.z - mu) * rstd * gv.z + bv.z;
    o.w = xv.w + (v.w - mu) * rstd * gv.w + bv.w;
    ((float4*)(out + (long)row * DD))[tid] = o;
}

// ---------------------------------------------------------------------------
// launch
// ---------------------------------------------------------------------------
extern "C" void kernel_launch(void* const* d_in, const int* in_sizes, int n_in,
                              void* d_out, int out_size)
{
    const float* x   = (const float*)d_in[0];
    const float* Wq  = (const float*)d_in[1];
    const float* Wk  = (const float*)d_in[2];
    const float* Wv  = (const float*)d_in[3];
    const float* Wo  = (const float*)d_in[4];
    const float* bo  = (const float*)d_in[5];
    const float* W1  = (const float*)d_in[6];
    const float* b1  = (const float*)d_in[7];
    const float* W2  = (const float*)d_in[8];
    const float* b2  = (const float*)d_in[9];
    const float* g1  = (const float*)d_in[10];
    const float* be1 = (const float*)d_in[11];
    const float* g2  = (const float*)d_in[12];
    const float* be2 = (const float*)d_in[13];
    float* out = (float*)d_out;

    float *packedW, *qkv, *obuf, *t1, *abuf, *h1;
    cudaGetSymbolAddress((void**)&packedW, g_packedW);
    cudaGetSymbolAddress((void**)&qkv,     g_qkv);
    cudaGetSymbolAddress((void**)&obuf,    g_obuf);
    cudaGetSymbolAddress((void**)&t1,      g_t1);
    cudaGetSymbolAddress((void**)&abuf,    g_abuf);
    cudaGetSymbolAddress((void**)&h1,      g_h1);

    const int ATTN_SMEM = (3 * 64 * 65 + 64 * 68) * 4;  // 67328 bytes
    cudaFuncSetAttribute(attn_kernel,
                         cudaFuncAttributeMaxDynamicSharedMemorySize, ATTN_SMEM);

    // 1) repack QKV weights
    repack_kernel<<<(DD * 3 * DD) / 256, 256>>>(Wq, Wk, Wv, packedW);

    // 2) qkv = x @ packedW          [4096,1024] x [1024,3072]
    sgemm_kernel<<<dim3(3 * DD / 128, MROWS / 128), 256>>>(
        x, DD, packedW, 3 * DD, qkv, 3 * DD, DD, nullptr, 0);

    // 3) attention
    attn_kernel<<<dim3(TT / 64, HH, BB), 256, ATTN_SMEM>>>(qkv, obuf);

    // 4) attn_out = o @ Wo + bo     [4096,1024] x [1024,1024]
    sgemm_kernel<<<dim3(DD / 128, MROWS / 128), 256>>>(
        obuf, DD, Wo, DD, t1, DD, DD, bo, 0);

    // 5) a = x + LN(attn_out; g1, be1)
    ln_kernel<<<MROWS, 256>>>(x, t1, g1, be1, abuf);

    // 6) h1 = relu(a @ W1 + b1)     [4096,1024] x [1024,4096]
    sgemm_kernel<<<dim3(FF / 128, MROWS / 128), 256>>>(
        abuf, DD, W1, FF, h1, FF, DD, b1, 1);

    // 7) f = h1 @ W2 + b2           [4096,4096] x [4096,1024]
    sgemm_kernel<<<dim3(DD / 128, MROWS / 128), 256>>>(
        h1, FF, W2, DD, t1, DD, FF, b2, 0);

    // 8) out = x + LN(f; g2, be2)
    ln_kernel<<<MROWS, 256>>>(x, t1, g2, be2, out);
}

// round 7
// speedup vs baseline: 2.3093x; 2.3093x over previous
#include <cuda_runtime.h>
#include <cuda_bf16.h>
#include <stdint.h>

// Problem constants
#define BB 2
#define TT 2048
#define DD 1024
#define HH 16
#define DHH 64
#define FF 4096
#define MROWS (BB*TT)   // 4096

// ---------------------------------------------------------------------------
// Scratch (device globals; no allocations allowed)
// ---------------------------------------------------------------------------
__device__ float g_packedW[DD * 3 * DD];       // [1024][3072] tf32-rounded
__device__ float g_xr[MROWS * DD];             // tf32-rounded x
__device__ float g_Wor[DD * DD];               // tf32-rounded Wo
__device__ float g_W1r[DD * FF];               // tf32-rounded W1
__device__ float g_W2r[FF * DD];               // tf32-rounded W2
__device__ float g_qkv[MROWS * 3 * DD];        // [4096][3072]
__device__ float g_obuf[MROWS * DD];           // attention out (tf32-rounded)
__device__ float g_t1[MROWS * DD];             // attn_out, later f
__device__ float g_abuf[MROWS * DD];           // a (tf32-rounded)
__device__ float g_h1[MROWS * FF];             // relu(a@W1+b1) (tf32-rounded)

__device__ __forceinline__ float to_tf32(float x) {
    float r;
    asm("cvt.rna.tf32.f32 %0, %1;" : "=f"(r) : "f"(x));
    return r;
}

__device__ __forceinline__ void cp_async16(unsigned int s, const void* g) {
    asm volatile("cp.async.cg.shared.global [%0], [%1], 16;\n" :: "r"(s), "l"(g));
}

// ---------------------------------------------------------------------------
// Repack Wq/Wk/Wv (H,D,DH) -> packed [D][3*D], tf32-rounded
// ---------------------------------------------------------------------------
__global__ __launch_bounds__(256) void repack_kernel(
    const float* __restrict__ Wq, const float* __restrict__ Wk,
    const float* __restrict__ Wv, float* __restrict__ packed)
{
    int idx = blockIdx.x * 256 + threadIdx.x;
    int d = idx / 3072;
    int n = idx - d * 3072;
    int w = n >> 10;
    int r = n & 1023;
    int h = r >> 6;
    int e = r & 63;
    const float* src = (w == 0) ? Wq : (w == 1) ? Wk : Wv;
    packed[idx] = to_tf32(src[h * (DD * DHH) + d * DHH + e]);
}

// ---------------------------------------------------------------------------
// Elementwise tf32 rounding (float4 granularity)
// ---------------------------------------------------------------------------
__global__ __launch_bounds__(256) void round_kernel(
    const float* __restrict__ in, float* __restrict__ out)
{
    int i = blockIdx.x * 256 + threadIdx.x;
    float4 v = ((const float4*)in)[i];
    v.x = to_tf32(v.x); v.y = to_tf32(v.y);
    v.z = to_tf32(v.z); v.w = to_tf32(v.w);
    ((float4*)out)[i] = v;
}

// ---------------------------------------------------------------------------
// TF32 tensor-core GEMM: C[M,N] = A[M,K]*B[K,N] (+bias)(+relu)(+round)
// 128x128x32 tiles, 256 threads, 8 warps each 64x32 (4x4 m16n8k8 tiles),
// cp.async double-buffered. A,B must be pre-rounded to tf32.
// ---------------------------------------------------------------------------
#define ASTRIDE 36
#define BSTRIDE 136
#define STAGE_FLOATS (128*ASTRIDE + 32*BSTRIDE)   // 4608 + 4352 = 8960

__global__ __launch_bounds__(256, 2) void tgemm_kernel(
    const float* __restrict__ A, int lda,
    const float* __restrict__ B, int ldb,
    float* __restrict__ C, int ldc,
    int K, const float* __restrict__ bias, int do_relu, int round_out)
{
    extern __shared__ float sm[];
    const int tid  = threadIdx.x;
    const int lane = tid & 31;
    const int warp = tid >> 5;
    const int gid  = lane >> 2;
    const int tig  = lane & 3;
    const int wm   = warp & 1;       // 0..1 (64-row chunk)
    const int wn   = warp >> 1;      // 0..3 (32-col chunk)
    const int rowBase = blockIdx.y * 128;
    const int colBase = blockIdx.x * 128;

    float acc[16][4];
    #pragma unroll
    for (int i = 0; i < 16; i++)
        #pragma unroll
        for (int j = 0; j < 4; j++) acc[i][j] = 0.f;

    // stage issue
    auto issue = [&](int stage, int k0) {
        float* As = sm + stage * STAGE_FLOATS;
        float* Bs = As + 128 * ASTRIDE;
        #pragma unroll
        for (int p = 0; p < 4; p++) {
            int idx = tid + p * 256;           // 0..1023
            int r = idx >> 3, c = idx & 7;     // A: 128 rows x 8 chunks
            const float* g = A + (long)(rowBase + r) * lda + k0 + c * 4;
            cp_async16((unsigned int)__cvta_generic_to_shared(As + r * ASTRIDE + c * 4), g);
        }
        #pragma unroll
        for (int p = 0; p < 4; p++) {
            int idx = tid + p * 256;
            int r = idx >> 5, c = idx & 31;    // B: 32 rows x 32 chunks
            const float* g = B + (long)(k0 + r) * ldb + colBase + c * 4;
            cp_async16((unsigned int)__cvta_generic_to_shared(Bs + r * BSTRIDE + c * 4), g);
        }
        asm volatile("cp.async.commit_group;\n");
    };

    issue(0, 0);
    const int nk = K / 32;

    for (int kt = 0; kt < nk; kt++) {
        if (kt + 1 < nk) {
            issue((kt + 1) & 1, (kt + 1) * 32);
            asm volatile("cp.async.wait_group 1;\n");
        } else {
            asm volatile("cp.async.wait_group 0;\n");
        }
        __syncthreads();

        const float* As = sm + (kt & 1) * STAGE_FLOATS;
        const float* Bs = As + 128 * ASTRIDE;

        #pragma unroll
        for (int ks = 0; ks < 4; ks++) {
            const int kk = ks * 8;
            unsigned int a[4][4], b[4][2];
            #pragma unroll
            for (int mt = 0; mt < 4; mt++) {
                int m0 = wm * 64 + mt * 16;
                a[mt][0] = __float_as_uint(As[(m0 + gid    ) * ASTRIDE + kk + tig    ]);
                a[mt][1] = __float_as_uint(As[(m0 + gid + 8) * ASTRIDE + kk + tig    ]);
                a[mt][2] = __float_as_uint(As[(m0 + gid    ) * ASTRIDE + kk + tig + 4]);
                a[mt][3] = __float_as_uint(As[(m0 + gid + 8) * ASTRIDE + kk + tig + 4]);
            }
            #pragma unroll
            for (int nt = 0; nt < 4; nt++) {
                int n0 = wn * 32 + nt * 8;
                b[nt][0] = __float_as_uint(Bs[(kk + tig    ) * BSTRIDE + n0 + gid]);
                b[nt][1] = __float_as_uint(Bs[(kk + tig + 4) * BSTRIDE + n0 + gid]);
            }
            #pragma unroll
            for (int mt = 0; mt < 4; mt++)
                #pragma unroll
                for (int nt = 0; nt < 4; nt++) {
                    float* c = acc[mt * 4 + nt];
                    asm volatile(
                        "mma.sync.aligned.m16n8k8.row.col.f32.tf32.tf32.f32 "
                        "{%0,%1,%2,%3},{%4,%5,%6,%7},{%8,%9},{%0,%1,%2,%3};\n"
                        : "+f"(c[0]), "+f"(c[1]), "+f"(c[2]), "+f"(c[3])
                        : "r"(a[mt][0]), "r"(a[mt][1]), "r"(a[mt][2]), "r"(a[mt][3]),
                          "r"(b[nt][0]), "r"(b[nt][1]));
                }
        }
        __syncthreads();
    }

    // epilogue
    #pragma unroll
    for (int mt = 0; mt < 4; mt++) {
        int r0 = rowBase + wm * 64 + mt * 16 + gid;
        #pragma unroll
        for (int nt = 0; nt < 4; nt++) {
            int c = colBase + wn * 32 + nt * 8 + tig * 2;
            float* v = acc[mt * 4 + nt];
            float o0 = v[0], o1 = v[1], o2 = v[2], o3 = v[3];
            if (bias) {
                float b0 = bias[c], b1 = bias[c + 1];
                o0 += b0; o1 += b1; o2 += b0; o3 += b1;
            }
            if (do_relu) {
                o0 = fmaxf(o0, 0.f); o1 = fmaxf(o1, 0.f);
                o2 = fmaxf(o2, 0.f); o3 = fmaxf(o3, 0.f);
            }
            if (round_out) {
                o0 = to_tf32(o0); o1 = to_tf32(o1);
                o2 = to_tf32(o2); o3 = to_tf32(o3);
            }
            *(float2*)&C[(long)r0 * ldc + c]       = make_float2(o0, o1);
            *(float2*)&C[(long)(r0 + 8) * ldc + c] = make_float2(o2, o3);
        }
    }
}

// ---------------------------------------------------------------------------
// Causal flash attention (fp32; epilogue rounds output to tf32).
// ---------------------------------------------------------------------------
__global__ __launch_bounds__(256) void attn_kernel(
    const float* __restrict__ qkv, float* __restrict__ o)
{
    extern __shared__ float sm[];
    float* Qt = sm;                 // [64][65]
    float* Kt = Qt + 64 * 65;
    float* Ps = Kt + 64 * 65;
    float* Vs = Ps + 64 * 65;       // [64][68]

    const int tid = threadIdx.x;
    const int tx = tid & 15;
    const int ty = tid >> 4;
    const int iq = (int)gridDim.x - 1 - (int)blockIdx.x;
    const int h = blockIdx.y;
    const int b = blockIdx.z;
    const int rowbase_g = iq * 64;
    const long base = (long)b * TT * 3072;

    {
        int r = tid >> 2;
        int dg = (tid & 3) * 16;
        const float* qp = qkv + base + (long)(rowbase_g + r) * 3072 + h * 64 + dg;
        #pragma unroll
        for (int it = 0; it < 4; it++) {
            float4 v = *(const float4*)(qp + it * 4);
            int d = dg + it * 4;
            Qt[(d + 0) * 65 + r] = v.x;
            Qt[(d + 1) * 65 + r] = v.y;
            Qt[(d + 2) * 65 + r] = v.z;
            Qt[(d + 3) * 65 + r] = v.w;
        }
    }

    float m[4], l[4], acc[4][4];
    #pragma unroll
    for (int i = 0; i < 4; i++) {
        m[i] = -1e30f; l[i] = 0.f;
        #pragma unroll
        for (int j = 0; j < 4; j++) acc[i][j] = 0.f;
    }
    const float scale = 0.125f;

    for (int jt = 0; jt <= iq; jt++) {
        __syncthreads();
        {
            int r = tid >> 2;
            int dg = (tid & 3) * 16;
            const float* kp = qkv + base + (long)(jt * 64 + r) * 3072 + 1024 + h * 64 + dg;
            const float* vp = kp + 1024;
            #pragma unroll
            for (int it = 0; it < 4; it++) {
                float4 kv = *(const float4*)(kp + it * 4);
                int d = dg + it * 4;
                Kt[(d + 0) * 65 + r] = kv.x;
                Kt[(d + 1) * 65 + r] = kv.y;
                Kt[(d + 2) * 65 + r] = kv.z;
                Kt[(d + 3) * 65 + r] = kv.w;
                float4 vv = *(const float4*)(vp + it * 4);
                *(float4*)&Vs[r * 68 + d] = vv;
            }
        }
        __syncthreads();

        float s[4][4];
        #pragma unroll
        for (int i = 0; i < 4; i++)
            #pragma unroll
            for (int j = 0; j < 4; j++) s[i][j] = 0.f;

        #pragma unroll 8
        for (int k = 0; k < 64; k++) {
            float qr[4], kc[4];
            #pragma unroll
            for (int i = 0; i < 4; i++) qr[i] = Qt[k * 65 + ty * 4 + i];
            #pragma unroll
            for (int j = 0; j < 4; j++) kc[j] = Kt[k * 65 + tx * 4 + j];
            #pragma unroll
            for (int i = 0; i < 4; i++)
                #pragma unroll
                for (int j = 0; j < 4; j++)
                    s[i][j] += qr[i] * kc[j];
        }

        #pragma unroll
        for (int i = 0; i < 4; i++) {
            int rg = rowbase_g + ty * 4 + i;
            float sv[4];
            float lm = -1e30f;
            #pragma unroll
            for (int j = 0; j < 4; j++) {
                int cg = jt * 64 + tx * 4 + j;
                sv[j] = (cg <= rg) ? s[i][j] * scale : -1e30f;
                lm = fmaxf(lm, sv[j]);
            }
            #pragma unroll
            for (int off = 8; off >= 1; off >>= 1)
                lm = fmaxf(lm, __shfl_xor_sync(0xffffffffu, lm, off));
            float mn = fmaxf(m[i], lm);
            float corr = __expf(m[i] - mn);
            float rs = 0.f;
            #pragma unroll
            for (int j = 0; j < 4; j++) {
                float p = __expf(sv[j] - mn);
                Ps[(tx * 4 + j) * 65 + ty * 4 + i] = p;
                rs += p;
            }
            #pragma unroll
            for (int off = 8; off >= 1; off >>= 1)
                rs += __shfl_xor_sync(0xffffffffu, rs, off);
            l[i] = l[i] * corr + rs;
            m[i] = mn;
            #pragma unroll
            for (int j = 0; j < 4; j++) acc[i][j] *= corr;
        }
        __syncthreads();

        #pragma unroll 4
        for (int k = 0; k < 64; k++) {
            float pr[4];
            #pragma unroll
            for (int i = 0; i < 4; i++) pr[i] = Ps[k * 65 + ty * 4 + i];
            float4 vv = *(const float4*)&Vs[k * 68 + tx * 4];
            #pragma unroll
            for (int i = 0; i < 4; i++) {
                acc[i][0] += pr[i] * vv.x;
                acc[i][1] += pr[i] * vv.y;
                acc[i][2] += pr[i] * vv.z;
                acc[i][3] += pr[i] * vv.w;
            }
        }
    }

    #pragma unroll
    for (int i = 0; i < 4; i++) {
        float inv = 1.f / l[i];
        int rg = rowbase_g + ty * 4 + i;
        float4 v;
        v.x = to_tf32(acc[i][0] * inv);
        v.y = to_tf32(acc[i][1] * inv);
        v.z = to_tf32(acc[i][2] * inv);
        v.w = to_tf32(acc[i][3] * inv);
        *(float4*)&o[((long)(b * TT + rg)) * DD + h * 64 + tx * 4] = v;
    }
}

// ---------------------------------------------------------------------------
// out = x + LayerNorm(y)*g + be ; optional tf32 rounding of the output.
// ---------------------------------------------------------------------------
__global__ __launch_bounds__(256) void ln_kernel(
    const float* __restrict__ x, const float* __restrict__ y,
    const float* __restrict__ g, const float* __restrict__ be,
    float* __restrict__ out, int round_out)
{
    int row = blockIdx.x;
    int tid = threadIdx.x;
    float4 v = ((const float4*)(y + (long)row * DD))[tid];
    float s  = v.x + v.y + v.z + v.w;
    float ss = v.x * v.x + v.y * v.y + v.z * v.z + v.w * v.w;
    #pragma unroll
    for (int off = 16; off >= 1; off >>= 1) {
        s  += __shfl_xor_sync(0xffffffffu, s,  off);
        ss += __shfl_xor_sync(0xffffffffu, ss, off);
    }
    __shared__ float sb[8], ssb[8];
    if ((tid & 31) == 0) { sb[tid >> 5] = s; ssb[tid >> 5] = ss; }
    __syncthreads();
    float tot = 0.f, tots = 0.f;
    #pragma unroll
    for (int w = 0; w < 8; w++) { tot += sb[w]; tots += ssb[w]; }
    float mu = tot * (1.f / 1024.f);
    float var = tots * (1.f / 1024.f) - mu * mu;
    float rstd = rsqrtf(var + 1e-5f);

    float4 xv = ((const float4*)(x + (long)row * DD))[tid];
    float4 gv = ((const float4*)g)[tid];
    float4 bv = ((const float4*)be)[tid];
    float4 o;
    o.x = xv.x + (v.x - mu) * rstd * gv.x + bv.x;
    o.y = xv.y + (v.y - mu) * rstd * gv.y + bv.y;
    o.z = xv.z + (v.z - mu) * rstd * gv.z + bv.z;
    o.w = xv.w + (v.w - mu) * rstd * gv.w + bv.w;
    if (round_out) {
        o.x = to_tf32(o.x); o.y = to_tf32(o.y);
        o.z = to_tf32(o.z); o.w = to_tf32(o.w);
    }
    ((float4*)(out + (long)row * DD))[tid] = o;
}

// ---------------------------------------------------------------------------
// launch
// ---------------------------------------------------------------------------
extern "C" void kernel_launch(void* const* d_in, const int* in_sizes, int n_in,
                              void* d_out, int out_size)
{
    const float* x   = (const float*)d_in[0];
    const float* Wq  = (const float*)d_in[1];
    const float* Wk  = (const float*)d_in[2];
    const float* Wv  = (const float*)d_in[3];
    const float* Wo  = (const float*)d_in[4];
    const float* bo  = (const float*)d_in[5];
    const float* W1  = (const float*)d_in[6];
    const float* b1  = (const float*)d_in[7];
    const float* W2  = (const float*)d_in[8];
    const float* b2  = (const float*)d_in[9];
    const float* g1  = (const float*)d_in[10];
    const float* be1 = (const float*)d_in[11];
    const float* g2  = (const float*)d_in[12];
    const float* be2 = (const float*)d_in[13];
    float* out = (float*)d_out;

    float *packedW, *xr, *Wor, *W1r, *W2r, *qkv, *obuf, *t1, *abuf, *h1;
    cudaGetSymbolAddress((void**)&packedW, g_packedW);
    cudaGetSymbolAddress((void**)&xr,      g_xr);
    cudaGetSymbolAddress((void**)&Wor,     g_Wor);
    cudaGetSymbolAddress((void**)&W1r,     g_W1r);
    cudaGetSymbolAddress((void**)&W2r,     g_W2r);
    cudaGetSymbolAddress((void**)&qkv,     g_qkv);
    cudaGetSymbolAddress((void**)&obuf,    g_obuf);
    cudaGetSymbolAddress((void**)&t1,      g_t1);
    cudaGetSymbolAddress((void**)&abuf,    g_abuf);
    cudaGetSymbolAddress((void**)&h1,      g_h1);

    const int ATTN_SMEM  = (3 * 64 * 65 + 64 * 68) * 4;     // 67328
    const int GEMM_SMEM  = 2 * STAGE_FLOATS * 4;            // 71680
    cudaFuncSetAttribute(attn_kernel,
                         cudaFuncAttributeMaxDynamicSharedMemorySize, ATTN_SMEM);
    cudaFuncSetAttribute(tgemm_kernel,
                         cudaFuncAttributeMaxDynamicSharedMemorySize, GEMM_SMEM);

    // 0) round inputs to tf32
    repack_kernel<<<(DD * 3 * DD) / 256, 256>>>(Wq, Wk, Wv, packedW);
    round_kernel<<<(MROWS * DD) / 1024, 256>>>(x,  xr);
    round_kernel<<<(DD * DD)    / 1024, 256>>>(Wo, Wor);
    round_kernel<<<(DD * FF)    / 1024, 256>>>(W1, W1r);
    round_kernel<<<(FF * DD)    / 1024, 256>>>(W2, W2r);

    // 1) qkv = xr @ packedW        [4096,1024]x[1024,3072]
    tgemm_kernel<<<dim3(3 * DD / 128, MROWS / 128), 256, GEMM_SMEM>>>(
        xr, DD, packedW, 3 * DD, qkv, 3 * DD, DD, nullptr, 0, 0);

    // 2) attention (rounds obuf)
    attn_kernel<<<dim3(TT / 64, HH, BB), 256, ATTN_SMEM>>>(qkv, obuf);

    // 3) attn_out = obuf @ Wor + bo
    tgemm_kernel<<<dim3(DD / 128, MROWS / 128), 256, GEMM_SMEM>>>(
        obuf, DD, Wor, DD, t1, DD, DD, bo, 0, 0);

    // 4) a = x + LN(attn_out), rounded (feeds W1 GEMM only)
    ln_kernel<<<MROWS, 256>>>(x, t1, g1, be1, abuf, 1);

    // 5) h1 = relu(a @ W1r + b1), rounded (feeds W2 GEMM only)
    tgemm_kernel<<<dim3(FF / 128, MROWS / 128), 256, GEMM_SMEM>>>(
        abuf, DD, W1r, FF, h1, FF, DD, b1, 1, 1);

    // 6) f = h1 @ W2r + b2
    tgemm_kernel<<<dim3(DD / 128, MROWS / 128), 256, GEMM_SMEM>>>(
        h1, FF, W2r, DD, t1, DD, FF, b2, 0, 0);

    // 7) out = x + LN(f)  (no rounding — final output)
    ln_kernel<<<MROWS, 256>>>(x, t1, g2, be2, out, 0);
}

// round 8
// speedup vs baseline: 3.2257x; 1.3968x over previous
#include <cuda_runtime.h>
#include <cuda_bf16.h>
#include <stdint.h>

// Problem constants
#define BB 2
#define TT 2048
#define DD 1024
#define HH 16
#define DHH 64
#define FF 4096
#define MROWS (BB*TT)   // 4096

// ---------------------------------------------------------------------------
// Scratch (device globals; no allocations allowed)
// ---------------------------------------------------------------------------
__device__ float g_packedW[DD * 3 * DD];       // [1024][3072] tf32-rounded
__device__ float g_xr[MROWS * DD];             // tf32-rounded x
__device__ float g_Wor[DD * DD];               // tf32-rounded Wo
__device__ float g_W1r[DD * FF];               // tf32-rounded W1
__device__ float g_W2r[FF * DD];               // tf32-rounded W2
__device__ float g_qkv[MROWS * 3 * DD];        // [4096][3072] (tf32-rounded)
__device__ float g_obuf[MROWS * DD];           // attention out (tf32-rounded)
__device__ float g_t1[MROWS * DD];             // attn_out, later f
__device__ float g_abuf[MROWS * DD];           // a (tf32-rounded)
__device__ float g_h1[MROWS * FF];             // relu(a@W1+b1) (tf32-rounded)

__device__ __forceinline__ float to_tf32(float x) {
    float r;
    asm("cvt.rna.tf32.f32 %0, %1;" : "=f"(r) : "f"(x));
    return r;
}

__device__ __forceinline__ void cp_async16(unsigned int s, const void* g) {
    asm volatile("cp.async.cg.shared.global [%0], [%1], 16;\n" :: "r"(s), "l"(g));
}

__device__ __forceinline__ void mma_tf32(float* c, const unsigned int* a,
                                         unsigned int b0, unsigned int b1) {
    asm volatile(
        "mma.sync.aligned.m16n8k8.row.col.f32.tf32.tf32.f32 "
        "{%0,%1,%2,%3},{%4,%5,%6,%7},{%8,%9},{%0,%1,%2,%3};\n"
        : "+f"(c[0]), "+f"(c[1]), "+f"(c[2]), "+f"(c[3])
        : "r"(a[0]), "r"(a[1]), "r"(a[2]), "r"(a[3]), "r"(b0), "r"(b1));
}

// ---------------------------------------------------------------------------
// Repack Wq/Wk/Wv (H,D,DH) -> packed [D][3*D], tf32-rounded
// ---------------------------------------------------------------------------
__global__ __launch_bounds__(256) void repack_kernel(
    const float* __restrict__ Wq, const float* __restrict__ Wk,
    const float* __restrict__ Wv, float* __restrict__ packed)
{
    int idx = blockIdx.x * 256 + threadIdx.x;
    int d = idx / 3072;
    int n = idx - d * 3072;
    int w = n >> 10;
    int r = n & 1023;
    int h = r >> 6;
    int e = r & 63;
    const float* src = (w == 0) ? Wq : (w == 1) ? Wk : Wv;
    packed[idx] = to_tf32(src[h * (DD * DHH) + d * DHH + e]);
}

// ---------------------------------------------------------------------------
// Elementwise tf32 rounding (float4 granularity)
// ---------------------------------------------------------------------------
__global__ __launch_bounds__(256) void round_kernel(
    const float* __restrict__ in, float* __restrict__ out)
{
    int i = blockIdx.x * 256 + threadIdx.x;
    float4 v = ((const float4*)in)[i];
    v.x = to_tf32(v.x); v.y = to_tf32(v.y);
    v.z = to_tf32(v.z); v.w = to_tf32(v.w);
    ((float4*)out)[i] = v;
}

// ---------------------------------------------------------------------------
// TF32 tensor-core GEMM: C[M,N] = A[M,K]*B[K,N] (+bias)(+relu)(+round)
// 128x128x32 tiles, 256 threads, 8 warps each 64x32 (4x4 m16n8k8 tiles),
// cp.async double-buffered. A,B must be pre-rounded to tf32.
// ---------------------------------------------------------------------------
#define ASTRIDE 36
#define BSTRIDE 136
#define STAGE_FLOATS (128*ASTRIDE + 32*BSTRIDE)   // 4608 + 4352 = 8960

__global__ __launch_bounds__(256, 2) void tgemm_kernel(
    const float* __restrict__ A, int lda,
    const float* __restrict__ B, int ldb,
    float* __restrict__ C, int ldc,
    int K, const float* __restrict__ bias, int do_relu, int round_out)
{
    extern __shared__ float sm[];
    const int tid  = threadIdx.x;
    const int lane = tid & 31;
    const int warp = tid >> 5;
    const int gid  = lane >> 2;
    const int tig  = lane & 3;
    const int wm   = warp & 1;       // 0..1 (64-row chunk)
    const int wn   = warp >> 1;      // 0..3 (32-col chunk)
    const int rowBase = blockIdx.y * 128;
    const int colBase = blockIdx.x * 128;

    float acc[16][4];
    #pragma unroll
    for (int i = 0; i < 16; i++)
        #pragma unroll
        for (int j = 0; j < 4; j++) acc[i][j] = 0.f;

    auto issue = [&](int stage, int k0) {
        float* As = sm + stage * STAGE_FLOATS;
        float* Bs = As + 128 * ASTRIDE;
        #pragma unroll
        for (int p = 0; p < 4; p++) {
            int idx = tid + p * 256;           // 0..1023
            int r = idx >> 3, c = idx & 7;     // A: 128 rows x 8 chunks
            const float* g = A + (long)(rowBase + r) * lda + k0 + c * 4;
            cp_async16((unsigned int)__cvta_generic_to_shared(As + r * ASTRIDE + c * 4), g);
        }
        #pragma unroll
        for (int p = 0; p < 4; p++) {
            int idx = tid + p * 256;
            int r = idx >> 5, c = idx & 31;    // B: 32 rows x 32 chunks
            const float* g = B + (long)(k0 + r) * ldb + colBase + c * 4;
            cp_async16((unsigned int)__cvta_generic_to_shared(Bs + r * BSTRIDE + c * 4), g);
        }
        asm volatile("cp.async.commit_group;\n");
    };

    issue(0, 0);
    const int nk = K / 32;

    for (int kt = 0; kt < nk; kt++) {
        if (kt + 1 < nk) {
            issue((kt + 1) & 1, (kt + 1) * 32);
            asm volatile("cp.async.wait_group 1;\n");
        } else {
            asm volatile("cp.async.wait_group 0;\n");
        }
        __syncthreads();

        const float* As = sm + (kt & 1) * STAGE_FLOATS;
        const float* Bs = As + 128 * ASTRIDE;

        #pragma unroll
        for (int ks = 0; ks < 4; ks++) {
            const int kk = ks * 8;
            unsigned int a[4][4], b[4][2];
            #pragma unroll
            for (int mt = 0; mt < 4; mt++) {
                int m0 = wm * 64 + mt * 16;
                a[mt][0] = __float_as_uint(As[(m0 + gid    ) * ASTRIDE + kk + tig    ]);
                a[mt][1] = __float_as_uint(As[(m0 + gid + 8) * ASTRIDE + kk + tig    ]);
                a[mt][2] = __float_as_uint(As[(m0 + gid    ) * ASTRIDE + kk + tig + 4]);
                a[mt][3] = __float_as_uint(As[(m0 + gid + 8) * ASTRIDE + kk + tig + 4]);
            }
            #pragma unroll
            for (int nt = 0; nt < 4; nt++) {
                int n0 = wn * 32 + nt * 8;
                b[nt][0] = __float_as_uint(Bs[(kk + tig    ) * BSTRIDE + n0 + gid]);
                b[nt][1] = __float_as_uint(Bs[(kk + tig + 4) * BSTRIDE + n0 + gid]);
            }
            #pragma unroll
            for (int mt = 0; mt < 4; mt++)
                #pragma unroll
                for (int nt = 0; nt < 4; nt++)
                    mma_tf32(acc[mt * 4 + nt], a[mt], b[nt][0], b[nt][1]);
        }
        __syncthreads();
    }

    // epilogue
    #pragma unroll
    for (int mt = 0; mt < 4; mt++) {
        int r0 = rowBase + wm * 64 + mt * 16 + gid;
        #pragma unroll
        for (int nt = 0; nt < 4; nt++) {
            int c = colBase + wn * 32 + nt * 8 + tig * 2;
            float* v = acc[mt * 4 + nt];
            float o0 = v[0], o1 = v[1], o2 = v[2], o3 = v[3];
            if (bias) {
                float b0 = bias[c], b1 = bias[c + 1];
                o0 += b0; o1 += b1; o2 += b0; o3 += b1;
            }
            if (do_relu) {
                o0 = fmaxf(o0, 0.f); o1 = fmaxf(o1, 0.f);
                o2 = fmaxf(o2, 0.f); o3 = fmaxf(o3, 0.f);
            }
            if (round_out) {
                o0 = to_tf32(o0); o1 = to_tf32(o1);
                o2 = to_tf32(o2); o3 = to_tf32(o3);
            }
            *(float2*)&C[(long)r0 * ldc + c]       = make_float2(o0, o1);
            *(float2*)&C[(long)(r0 + 8) * ldc + c] = make_float2(o2, o3);
        }
    }
}

// ---------------------------------------------------------------------------
// Tensor-core causal flash attention.
// Block: 256 threads (8 warps), Q tile = 128 rows; each warp owns 16 rows.
// K tile = 64. S = Q K^T and O += P V both via m16n8k8 tf32 mma.
// qkv must be tf32-rounded. Output tf32-rounded.
// Smem layout (stride 68 floats -> conflict-free fragment loads):
//   Qs[128][68], Kt[64 dims][68 tokens], Vs[64 tok][68 dims], Ps[128][68]
// ---------------------------------------------------------------------------
#define ATS 68
#define ATTN_SMEM_FLOATS ((128 + 64 + 64 + 128) * ATS)   // 26112 floats

__global__ __launch_bounds__(256) void attn_mma_kernel(
    const float* __restrict__ qkv, float* __restrict__ obuf)
{
    extern __shared__ float sm[];
    float* Qs = sm;                    // [128][ATS]
    float* Kt = Qs + 128 * ATS;        // [64][ATS]   K^T: [dim][token]
    float* Vs = Kt + 64 * ATS;         // [64][ATS]   V:   [token][dim]
    float* Ps = Vs + 64 * ATS;         // [128][ATS]

    const int tid  = threadIdx.x;
    const int lane = tid & 31;
    const int warp = tid >> 5;
    const int gid  = lane >> 2;
    const int tig  = lane & 3;
    const int iq   = (int)gridDim.x - 1 - (int)blockIdx.x;  // heavy first
    const int h    = blockIdx.y;
    const int b    = blockIdx.z;
    const int rowbase = iq * 128;
    const int mrow = warp * 16;
    const long base = (long)b * TT * 3072;

    // Load Q tile [128][64]
    {
        int r  = tid >> 1;           // 0..127
        int dg = (tid & 1) * 32;     // 0 / 32
        const float* qp = qkv + base + (long)(rowbase + r) * 3072 + h * 64 + dg;
        float* dst = Qs + r * ATS + dg;
        #pragma unroll
        for (int it = 0; it < 8; it++)
            *(float4*)(dst + it * 4) = *(const float4*)(qp + it * 4);
    }

    // log2-domain softmax state; scale = DH^-0.5 * log2(e)
    const float sscale = 0.125f * 1.44269504f;
    float m0 = -1e30f, m1 = -1e30f, l0 = 0.f, l1 = 0.f;
    float o_[8][4];
    #pragma unroll
    for (int nt = 0; nt < 8; nt++)
        #pragma unroll
        for (int j = 0; j < 4; j++) o_[nt][j] = 0.f;

    const int row0 = rowbase + mrow + gid;      // this thread's two rows
    const int row1 = row0 + 8;
    const int jmax = (rowbase >> 6) + 1;

    for (int jt = 0; jt <= jmax; jt++) {
        __syncthreads();
        // Load K tile (transposed) and V tile
        {
            int r  = tid >> 2;          // token 0..63
            int dg = (tid & 3) * 16;    // dim chunk
            const float* kp = qkv + base + (long)(jt * 64 + r) * 3072 + 1024 + h * 64 + dg;
            const float* vp = kp + 1024;
            #pragma unroll
            for (int it = 0; it < 4; it++) {
                float4 kv = *(const float4*)(kp + it * 4);
                int d = dg + it * 4;
                Kt[(d + 0) * ATS + r] = kv.x;
                Kt[(d + 1) * ATS + r] = kv.y;
                Kt[(d + 2) * ATS + r] = kv.z;
                Kt[(d + 3) * ATS + r] = kv.w;
                float4 vv = *(const float4*)(vp + it * 4);
                *(float4*)&Vs[r * ATS + d] = vv;
            }
        }
        __syncthreads();

        // Per-warp skip of fully-masked tiles
        if (jt * 64 > rowbase + mrow + 15) continue;

        // S = Q K^T : s[8 ntiles][4]
        float s[8][4];
        #pragma unroll
        for (int nt = 0; nt < 8; nt++)
            #pragma unroll
            for (int j = 0; j < 4; j++) s[nt][j] = 0.f;

        #pragma unroll
        for (int kk = 0; kk < 64; kk += 8) {
            unsigned int a[4];
            a[0] = __float_as_uint(Qs[(mrow + gid    ) * ATS + kk + tig    ]);
            a[1] = __float_as_uint(Qs[(mrow + gid + 8) * ATS + kk + tig    ]);
            a[2] = __float_as_uint(Qs[(mrow + gid    ) * ATS + kk + tig + 4]);
            a[3] = __float_as_uint(Qs[(mrow + gid + 8) * ATS + kk + tig + 4]);
            #pragma unroll
            for (int nt = 0; nt < 8; nt++) {
                unsigned int b0 = __float_as_uint(Kt[(kk + tig    ) * ATS + nt * 8 + gid]);
                unsigned int b1 = __float_as_uint(Kt[(kk + tig + 4) * ATS + nt * 8 + gid]);
                mma_tf32(s[nt], a, b0, b1);
            }
        }

        // scale + causal mask (log2 domain)
        const bool need_mask = (jt * 64 + 63 > rowbase + mrow);
        #pragma unroll
        for (int nt = 0; nt < 8; nt++) {
            int col = jt * 64 + nt * 8 + tig * 2;
            if (need_mask) {
                s[nt][0] = (col     <= row0) ? s[nt][0] * sscale : -1e30f;
                s[nt][1] = (col + 1 <= row0) ? s[nt][1] * sscale : -1e30f;
                s[nt][2] = (col     <= row1) ? s[nt][2] * sscale : -1e30f;
                s[nt][3] = (col + 1 <= row1) ? s[nt][3] * sscale : -1e30f;
            } else {
                s[nt][0] *= sscale; s[nt][1] *= sscale;
                s[nt][2] *= sscale; s[nt][3] *= sscale;
            }
        }

        // row maxima (reduce over tig lanes: xor 1, 2)
        float tm0 = -1e30f, tm1 = -1e30f;
        #pragma unroll
        for (int nt = 0; nt < 8; nt++) {
            tm0 = fmaxf(tm0, fmaxf(s[nt][0], s[nt][1]));
            tm1 = fmaxf(tm1, fmaxf(s[nt][2], s[nt][3]));
        }
        tm0 = fmaxf(tm0, __shfl_xor_sync(0xffffffffu, tm0, 1));
        tm0 = fmaxf(tm0, __shfl_xor_sync(0xffffffffu, tm0, 2));
        tm1 = fmaxf(tm1, __shfl_xor_sync(0xffffffffu, tm1, 1));
        tm1 = fmaxf(tm1, __shfl_xor_sync(0xffffffffu, tm1, 2));

        float mn0 = fmaxf(m0, tm0);
        float mn1 = fmaxf(m1, tm1);
        float corr0 = exp2f(m0 - mn0);
        float corr1 = exp2f(m1 - mn1);

        float rs0 = 0.f, rs1 = 0.f;
        #pragma unroll
        for (int nt = 0; nt < 8; nt++) {
            float p00 = to_tf32(exp2f(s[nt][0] - mn0));
            float p01 = to_tf32(exp2f(s[nt][1] - mn0));
            float p10 = to_tf32(exp2f(s[nt][2] - mn1));
            float p11 = to_tf32(exp2f(s[nt][3] - mn1));
            rs0 += p00 + p01;
            rs1 += p10 + p11;
            *(float2*)&Ps[(mrow + gid    ) * ATS + nt * 8 + tig * 2] = make_float2(p00, p01);
            *(float2*)&Ps[(mrow + gid + 8) * ATS + nt * 8 + tig * 2] = make_float2(p10, p11);
        }
        rs0 += __shfl_xor_sync(0xffffffffu, rs0, 1);
        rs0 += __shfl_xor_sync(0xffffffffu, rs0, 2);
        rs1 += __shfl_xor_sync(0xffffffffu, rs1, 1);
        rs1 += __shfl_xor_sync(0xffffffffu, rs1, 2);

        l0 = l0 * corr0 + rs0;  m0 = mn0;
        l1 = l1 * corr1 + rs1;  m1 = mn1;
        #pragma unroll
        for (int nt = 0; nt < 8; nt++) {
            o_[nt][0] *= corr0; o_[nt][1] *= corr0;
            o_[nt][2] *= corr1; o_[nt][3] *= corr1;
        }
        __syncwarp();   // make this warp's Ps stores visible to its own lanes

        // O += P V
        #pragma unroll
        for (int kk = 0; kk < 64; kk += 8) {
            unsigned int a[4];
            a[0] = __float_as_uint(Ps[(mrow + gid    ) * ATS + kk + tig    ]);
            a[1] = __float_as_uint(Ps[(mrow + gid + 8) * ATS + kk + tig    ]);
            a[2] = __float_as_uint(Ps[(mrow + gid    ) * ATS + kk + tig + 4]);
            a[3] = __float_as_uint(Ps[(mrow + gid + 8) * ATS + kk + tig + 4]);
            #pragma unroll
            for (int nt = 0; nt < 8; nt++) {
                unsigned int b0 = __float_as_uint(Vs[(kk + tig    ) * ATS + nt * 8 + gid]);
                unsigned int b1 = __float_as_uint(Vs[(kk + tig + 4) * ATS + nt * 8 + gid]);
                mma_tf32(o_[nt], a, b0, b1);
            }
        }
    }

    // epilogue: normalize and store (tf32-rounded; feeds Wo GEMM)
    float inv0 = 1.f / l0;
    float inv1 = 1.f / l1;
    #pragma unroll
    for (int nt = 0; nt < 8; nt++) {
        int c = h * 64 + nt * 8 + tig * 2;
        *(float2*)&obuf[(long)(b * TT + row0) * DD + c] =
            make_float2(to_tf32(o_[nt][0] * inv0), to_tf32(o_[nt][1] * inv0));
        *(float2*)&obuf[(long)(b * TT + row1) * DD + c] =
            make_float2(to_tf32(o_[nt][2] * inv1), to_tf32(o_[nt][3] * inv1));
    }
}

// ---------------------------------------------------------------------------
// out = x + LayerNorm(y)*g + be ; optional tf32 rounding of the output.
// ---------------------------------------------------------------------------
__global__ __launch_bounds__(256) void ln_kernel(
    const float* __restrict__ x, const float* __restrict__ y,
    const float* __restrict__ g, const float* __restrict__ be,
    float* __restrict__ out, int round_out)
{
    int row = blockIdx.x;
    int tid = threadIdx.x;
    float4 v = ((const float4*)(y + (long)row * DD))[tid];
    float s  = v.x + v.y + v.z + v.w;
    float ss = v.x * v.x + v.y * v.y + v.z * v.z + v.w * v.w;
    #pragma unroll
    for (int off = 16; off >= 1; off >>= 1) {
        s  += __shfl_xor_sync(0xffffffffu, s,  off);
        ss += __shfl_xor_sync(0xffffffffu, ss, off);
    }
    __shared__ float sb[8], ssb[8];
    if ((tid & 31) == 0) { sb[tid >> 5] = s; ssb[tid >> 5] = ss; }
    __syncthreads();
    float tot = 0.f, tots = 0.f;
    #pragma unroll
    for (int w = 0; w < 8; w++) { tot += sb[w]; tots += ssb[w]; }
    float mu = tot * (1.f / 1024.f);
    float var = tots * (1.f / 1024.f) - mu * mu;
    float rstd = rsqrtf(var + 1e-5f);

    float4 xv = ((const float4*)(x + (long)row * DD))[tid];
    float4 gv = ((const float4*)g)[tid];
    float4 bv = ((const float4*)be)[tid];
    float4 o;
    o.x = xv.x + (v.x - mu) * rstd * gv.x + bv.x;
    o.y = xv.y + (v.y - mu) * rstd * gv.y + bv.y;
    o.z = xv.z + (v.z - mu) * rstd * gv.z + bv.z;
    o.w = xv.w + (v.w - mu) * rstd * gv.w + bv.w;
    if (round_out) {
        o.x = to_tf32(o.x); o.y = to_tf32(o.y);
        o.z = to_tf32(o.z); o.w = to_tf32(o.w);
    }
    ((float4*)(out + (long)row * DD))[tid] = o;
}

// ---------------------------------------------------------------------------
// launch
// ---------------------------------------------------------------------------
extern "C" void kernel_launch(void* const* d_in, const int* in_sizes, int n_in,
                              void* d_out, int out_size)
{
    const float* x   = (const float*)d_in[0];
    const float* Wq  = (const float*)d_in[1];
    const float* Wk  = (const float*)d_in[2];
    const float* Wv  = (const float*)d_in[3];
    const float* Wo  = (const float*)d_in[4];
    const float* bo  = (const float*)d_in[5];
    const float* W1  = (const float*)d_in[6];
    const float* b1  = (const float*)d_in[7];
    const float* W2  = (const float*)d_in[8];
    const float* b2  = (const float*)d_in[9];
    const float* g1  = (const float*)d_in[10];
    const float* be1 = (const float*)d_in[11];
    const float* g2  = (const float*)d_in[12];
    const float* be2 = (const float*)d_in[13];
    float* out = (float*)d_out;

    float *packedW, *xr, *Wor, *W1r, *W2r, *qkv, *obuf, *t1, *abuf, *h1;
    cudaGetSymbolAddress((void**)&packedW, g_packedW);
    cudaGetSymbolAddress((void**)&xr,      g_xr);
    cudaGetSymbolAddress((void**)&Wor,     g_Wor);
    cudaGetSymbolAddress((void**)&W1r,     g_W1r);
    cudaGetSymbolAddress((void**)&W2r,     g_W2r);
    cudaGetSymbolAddress((void**)&qkv,     g_qkv);
    cudaGetSymbolAddress((void**)&obuf,    g_obuf);
    cudaGetSymbolAddress((void**)&t1,      g_t1);
    cudaGetSymbolAddress((void**)&abuf,    g_abuf);
    cudaGetSymbolAddress((void**)&h1,      g_h1);

    const int ATTN_SMEM  = ATTN_SMEM_FLOATS * 4;            // 104448
    const int GEMM_SMEM  = 2 * STAGE_FLOATS * 4;            // 71680
    cudaFuncSetAttribute(attn_mma_kernel,
                         cudaFuncAttributeMaxDynamicSharedMemorySize, ATTN_SMEM);
    cudaFuncSetAttribute(tgemm_kernel,
                         cudaFuncAttributeMaxDynamicSharedMemorySize, GEMM_SMEM);

    // 0) round inputs to tf32
    repack_kernel<<<(DD * 3 * DD) / 256, 256>>>(Wq, Wk, Wv, packedW);
    round_kernel<<<(MROWS * DD) / 1024, 256>>>(x,  xr);
    round_kernel<<<(DD * DD)    / 1024, 256>>>(Wo, Wor);
    round_kernel<<<(DD * FF)    / 1024, 256>>>(W1, W1r);
    round_kernel<<<(FF * DD)    / 1024, 256>>>(W2, W2r);

    // 1) qkv = xr @ packedW  (rounded: feeds tensor-core attention)
    tgemm_kernel<<<dim3(3 * DD / 128, MROWS / 128), 256, GEMM_SMEM>>>(
        xr, DD, packedW, 3 * DD, qkv, 3 * DD, DD, nullptr, 0, 1);

    // 2) attention (tensor-core, rounds obuf)
    attn_mma_kernel<<<dim3(TT / 128, HH, BB), 256, ATTN_SMEM>>>(qkv, obuf);

    // 3) attn_out = obuf @ Wor + bo
    tgemm_kernel<<<dim3(DD / 128, MROWS / 128), 256, GEMM_SMEM>>>(
        obuf, DD, Wor, DD, t1, DD, DD, bo, 0, 0);

    // 4) a = x + LN(attn_out), rounded (feeds W1 GEMM)
    ln_kernel<<<MROWS, 256>>>(x, t1, g1, be1, abuf, 1);

    // 5) h1 = relu(a @ W1r + b1), rounded (feeds W2 GEMM)
    tgemm_kernel<<<dim3(FF / 128, MROWS / 128), 256, GEMM_SMEM>>>(
        abuf, DD, W1r, FF, h1, FF, DD, b1, 1, 1);

    // 6) f = h1 @ W2r + b2
    tgemm_kernel<<<dim3(DD / 128, MROWS / 128), 256, GEMM_SMEM>>>(
        h1, FF, W2r, DD, t1, DD, FF, b2, 0, 0);

    // 7) out = x + LN(f)
    ln_kernel<<<MROWS, 256>>>(x, t1, g2, be2, out, 0);
}

// round 10
// speedup vs baseline: 6.3911x; 1.9813x over previous
#include <cuda_runtime.h>
#include <cuda_fp16.h>
#include <stdint.h>

// Problem constants
#define BB 2
#define TT 2048
#define DD 1024
#define HH 16
#define DHH 64
#define FF 4096
#define MROWS (BB*TT)   // 4096

// ---------------------------------------------------------------------------
// Scratch (device globals; no allocations allowed)
// ---------------------------------------------------------------------------
__device__ __align__(16) __half g_packedWT[3 * DD * DD]; // [3072][1024] K-major
__device__ __align__(16) __half g_xh[MROWS * DD];        // half x
__device__ __align__(16) __half g_WoT[DD * DD];          // [1024][1024] K-major
__device__ __align__(16) __half g_W1T[FF * DD];          // [4096][1024] K-major
__device__ __align__(16) __half g_W2T[DD * FF];          // [1024][4096] K-major
__device__ __align__(16) __half g_qkv[MROWS * 3 * DD];   // [4096][3072]
__device__ __align__(16) __half g_obuf[MROWS * DD];      // attention out
__device__ __align__(16) __half g_abuf[MROWS * DD];      // a (half)
__device__ __align__(16) __half g_h1[MROWS * FF];        // relu(a@W1+b1)
__device__ float g_t1[MROWS * DD];                       // f32 LN inputs

__device__ __forceinline__ void cp_async16(unsigned int s, const void* g) {
    asm volatile("cp.async.cg.shared.global [%0], [%1], 16;\n" :: "r"(s), "l"(g));
}

__device__ __forceinline__ void mma_f16(float* c, const unsigned int* a,
                                        unsigned int b0, unsigned int b1) {
    asm volatile(
        "mma.sync.aligned.m16n8k16.row.col.f32.f16.f16.f32 "
        "{%0,%1,%2,%3},{%4,%5,%6,%7},{%8,%9},{%0,%1,%2,%3};\n"
        : "+f"(c[0]), "+f"(c[1]), "+f"(c[2]), "+f"(c[3])
        : "r"(a[0]), "r"(a[1]), "r"(a[2]), "r"(a[3]), "r"(b0), "r"(b1));
}

// ---------------------------------------------------------------------------
// f32 -> half conversion, 8 elements/thread
// ---------------------------------------------------------------------------
__global__ __launch_bounds__(256) void tohalf_kernel(
    const float* __restrict__ in, __half* __restrict__ out)
{
    int i = blockIdx.x * 256 + threadIdx.x;
    float4 v0 = ((const float4*)in)[2 * i];
    float4 v1 = ((const float4*)in)[2 * i + 1];
    __half2 h[4];
    h[0] = __floats2half2_rn(v0.x, v0.y);
    h[1] = __floats2half2_rn(v0.z, v0.w);
    h[2] = __floats2half2_rn(v1.x, v1.y);
    h[3] = __floats2half2_rn(v1.z, v1.w);
    *(uint4*)&out[i * 8] = *(uint4*)h;
}

// ---------------------------------------------------------------------------
// Tiled transpose + half convert: dst[c][r] = half(src[r][c]).
// grid (cols/32, rows/32), 256 threads.
// ---------------------------------------------------------------------------
__global__ __launch_bounds__(256) void transpose_kernel(
    const float* __restrict__ src, int rows, int cols, __half* __restrict__ dst)
{
    __shared__ float t[32][33];
    int bx = blockIdx.x * 32, by = blockIdx.y * 32;
    int tx = threadIdx.x & 31, ty = threadIdx.x >> 5;
    #pragma unroll
    for (int i = 0; i < 4; i++)
        t[ty + i * 8][tx] = src[(long)(by + ty + i * 8) * cols + bx + tx];
    __syncthreads();
    #pragma unroll
    for (int i = 0; i < 4; i++)
        dst[(long)(bx + ty + i * 8) * rows + by + tx] = __float2half(t[tx][ty + i * 8]);
}

// ---------------------------------------------------------------------------
// QKV weight transpose: Wq/Wk/Wv (H,D,DH) -> packedWT [3072][1024] K-major half.
// Row n = w*1024 + h*64 + e holds W[h][:][e]. grid (2, 32, 48).
// ---------------------------------------------------------------------------
__global__ __launch_bounds__(256) void transpose_qkv_kernel(
    const float* __restrict__ Wq, const float* __restrict__ Wk,
    const float* __restrict__ Wv, __half* __restrict__ dst)
{
    __shared__ float t[32][33];
    int z = blockIdx.z;
    int w = z >> 4, h = z & 15;
    const float* src = ((w == 0) ? Wq : (w == 1) ? Wk : Wv) + (long)h * (DD * DHH);
    int bx = blockIdx.x * 32, by = blockIdx.y * 32;
    int tx = threadIdx.x & 31, ty = threadIdx.x >> 5;
    #pragma unroll
    for (int i = 0; i < 4; i++)
        t[ty + i * 8][tx] = src[(long)(by + ty + i * 8) * DHH + bx + tx];
    __syncthreads();
    #pragma unroll
    for (int i = 0; i < 4; i++)
        dst[(long)(w * 1024 + h * 64 + bx + ty + i * 8) * DD + by + tx] =
            __float2half(t[tx][ty + i * 8]);
}

// ---------------------------------------------------------------------------
// fp16 tensor-core GEMM: C = A[M,K] * BT[N,K]^T (+bias)(+relu)
// A row-major half; BT row-major half (K-major weights).
// 128x128 tile, K-chunk 64, 2-stage cp.async, 8 warps each 64x32.
// Output: half to Ch if non-null, else f32 to Cf.
// ---------------------------------------------------------------------------
#define HSTR 72                           // halves per smem row (64 + 8 pad)
#define HSTAGE_B (128 * HSTR * 2 * 2)     // A + B per stage = 36864 bytes
#define HGEMM_SMEM (2 * HSTAGE_B)         // 73728

__global__ __launch_bounds__(256, 2) void hgemm_kernel(
    const __half* __restrict__ A, int lda,
    const __half* __restrict__ BT, int K,
    float* __restrict__ Cf, __half* __restrict__ Ch, int ldc,
    const float* __restrict__ bias, int do_relu)
{
    extern __shared__ __align__(16) char dsm[];
    const int tid  = threadIdx.x;
    const int lane = tid & 31;
    const int warp = tid >> 5;
    const int gid  = lane >> 2;
    const int tig  = lane & 3;
    const int wm   = warp & 1;
    const int wn   = warp >> 1;
    const int rowBase = blockIdx.y * 128;
    const int colBase = blockIdx.x * 128;
    const unsigned int smem_u = (unsigned int)__cvta_generic_to_shared(dsm);

    float acc[16][4];
    #pragma unroll
    for (int i = 0; i < 16; i++)
        #pragma unroll
        for (int j = 0; j < 4; j++) acc[i][j] = 0.f;

    auto issue = [&](int stage, int k0) {
        unsigned int st = smem_u + stage * HSTAGE_B;
        #pragma unroll
        for (int p = 0; p < 4; p++) {            // A: 128 rows x 8 x 16B
            int i = tid + p * 256;
            int r = i >> 3, q = i & 7;
            cp_async16(st + r * (HSTR * 2) + q * 16,
                       A + (long)(rowBase + r) * lda + k0 + q * 8);
        }
        #pragma unroll
        for (int p = 0; p < 4; p++) {            // B: 128 n-rows x 8 x 16B
            int i = tid + p * 256;
            int n = i >> 3, q = i & 7;
            cp_async16(st + 128 * (HSTR * 2) + n * (HSTR * 2) + q * 16,
                       BT + (long)(colBase + n) * K + k0 + q * 8);
        }
        asm volatile("cp.async.commit_group;\n");
    };

    issue(0, 0);
    const int nk = K / 64;

    for (int kt = 0; kt < nk; kt++) {
        if (kt + 1 < nk) {
            issue((kt + 1) & 1, (kt + 1) * 64);
            asm volatile("cp.async.wait_group 1;\n");
        } else {
            asm volatile("cp.async.wait_group 0;\n");
        }
        __syncthreads();

        const __half* As = (const __half*)(dsm + (kt & 1) * HSTAGE_B);
        const __half* Bs = As + 128 * HSTR;

        #pragma unroll
        for (int ks = 0; ks < 4; ks++) {
            const int kk = ks * 16;
            unsigned int a[4][4], b[4][2];
            #pragma unroll
            for (int mt = 0; mt < 4; mt++) {
                int m0 = wm * 64 + mt * 16;
                a[mt][0] = *(const unsigned int*)&As[(m0 + gid    ) * HSTR + kk + 2 * tig];
                a[mt][1] = *(const unsigned int*)&As[(m0 + gid + 8) * HSTR + kk + 2 * tig];
                a[mt][2] = *(const unsigned int*)&As[(m0 + gid    ) * HSTR + kk + 8 + 2 * tig];
                a[mt][3] = *(const unsigned int*)&As[(m0 + gid + 8) * HSTR + kk + 8 + 2 * tig];
            }
            #pragma unroll
            for (int nt = 0; nt < 4; nt++) {
                int n0 = wn * 32 + nt * 8;
                b[nt][0] = *(const unsigned int*)&Bs[(n0 + gid) * HSTR + kk + 2 * tig];
                b[nt][1] = *(const unsigned int*)&Bs[(n0 + gid) * HSTR + kk + 8 + 2 * tig];
            }
            #pragma unroll
            for (int mt = 0; mt < 4; mt++)
                #pragma unroll
                for (int nt = 0; nt < 4; nt++)
                    mma_f16(acc[mt * 4 + nt], a[mt], b[nt][0], b[nt][1]);
        }
        __syncthreads();
    }

    // epilogue
    #pragma unroll
    for (int mt = 0; mt < 4; mt++) {
        int r0 = rowBase + wm * 64 + mt * 16 + gid;
        #pragma unroll
        for (int nt = 0; nt < 4; nt++) {
            int c = colBase + wn * 32 + nt * 8 + tig * 2;
            float* v = acc[mt * 4 + nt];
            float o0 = v[0], o1 = v[1], o2 = v[2], o3 = v[3];
            if (bias) {
                float b0 = bias[c], b1 = bias[c + 1];
                o0 += b0; o1 += b1; o2 += b0; o3 += b1;
            }
            if (do_relu) {
                o0 = fmaxf(o0, 0.f); o1 = fmaxf(o1, 0.f);
                o2 = fmaxf(o2, 0.f); o3 = fmaxf(o3, 0.f);
            }
            if (Ch) {
                *(__half2*)&Ch[(long)r0 * ldc + c]       = __floats2half2_rn(o0, o1);
                *(__half2*)&Ch[(long)(r0 + 8) * ldc + c] = __floats2half2_rn(o2, o3);
            } else {
                *(float2*)&Cf[(long)r0 * ldc + c]       = make_float2(o0, o1);
                *(float2*)&Cf[(long)(r0 + 8) * ldc + c] = make_float2(o2, o3);
            }
        }
    }
}

// ---------------------------------------------------------------------------
// fp16 tensor-core causal flash attention.
// 256 threads (8 warps), Q tile 128 rows, warp owns 16 rows, K tile 64.
// Smem (half, stride 72): Qs[128], Ks[64 tok][dim], Vt[64 dim][tok], Ps[128].
// ---------------------------------------------------------------------------
#define ATTN_SMEM_BYTES ((128 + 64 + 64 + 128) * HSTR * 2)   // 55296

__global__ __launch_bounds__(256) void attn_h_kernel(
    const __half* __restrict__ qkv, __half* __restrict__ obuf)
{
    extern __shared__ __align__(16) __half hsm[];
    __half* Qs = hsm;                   // [128][HSTR]
    __half* Ks = Qs + 128 * HSTR;       // [64][HSTR]  K natural [token][dim]
    __half* Vt = Ks + 64 * HSTR;        // [64][HSTR]  V transposed [dim][token]
    __half* Ps = Vt + 64 * HSTR;        // [128][HSTR]

    const int tid  = threadIdx.x;
    const int lane = tid & 31;
    const int warp = tid >> 5;
    const int gid  = lane >> 2;
    const int tig  = lane & 3;
    const int iq   = (int)gridDim.x - 1 - (int)blockIdx.x;
    const int h    = blockIdx.y;
    const int b    = blockIdx.z;
    const int rowbase = iq * 128;
    const int mrow = warp * 16;
    const long base = (long)b * TT * 3072;

    // Load Q tile [128][64] halves
    {
        int r  = tid >> 1;
        int dg = (tid & 1) * 32;
        const __half* qp = qkv + base + (long)(rowbase + r) * 3072 + h * 64 + dg;
        #pragma unroll
        for (int it = 0; it < 4; it++)
            *(uint4*)&Qs[r * HSTR + dg + it * 8] = *(const uint4*)(qp + it * 8);
    }

    const float sscale = 0.125f * 1.44269504f;
    float m0 = -1e30f, m1 = -1e30f, l0 = 0.f, l1 = 0.f;
    float o_[8][4];
    #pragma unroll
    for (int nt = 0; nt < 8; nt++)
        #pragma unroll
        for (int j = 0; j < 4; j++) o_[nt][j] = 0.f;

    const int row0 = rowbase + mrow + gid;
    const int row1 = row0 + 8;
    const int jmax = (rowbase >> 6) + 1;

    for (int jt = 0; jt <= jmax; jt++) {
        __syncthreads();
        // Load K (natural) and V (transposed)
        {
            int r  = tid >> 2;          // token 0..63
            int dg = (tid & 3) * 16;    // dim chunk
            const __half* kp = qkv + base + (long)(jt * 64 + r) * 3072 + 1024 + h * 64 + dg;
            const __half* vp = kp + 1024;
            #pragma unroll
            for (int it = 0; it < 2; it++)
                *(uint4*)&Ks[r * HSTR + dg + it * 8] = *(const uint4*)(kp + it * 8);
            #pragma unroll
            for (int it = 0; it < 2; it++) {
                uint4 raw = *(const uint4*)(vp + it * 8);
                __half tmp[8];
                *(uint4*)tmp = raw;
                #pragma unroll
                for (int j = 0; j < 8; j++)
                    Vt[(dg + it * 8 + j) * HSTR + r] = tmp[j];
            }
        }
        __syncthreads();

        if (jt * 64 > rowbase + mrow + 15) continue;

        // S = Q K^T
        float s[8][4];
        #pragma unroll
        for (int nt = 0; nt < 8; nt++)
            #pragma unroll
            for (int j = 0; j < 4; j++) s[nt][j] = 0.f;

        #pragma unroll
        for (int kk = 0; kk < 64; kk += 16) {
            unsigned int a[4];
            a[0] = *(const unsigned int*)&Qs[(mrow + gid    ) * HSTR + kk + 2 * tig];
            a[1] = *(const unsigned int*)&Qs[(mrow + gid + 8) * HSTR + kk + 2 * tig];
            a[2] = *(const unsigned int*)&Qs[(mrow + gid    ) * HSTR + kk + 8 + 2 * tig];
            a[3] = *(const unsigned int*)&Qs[(mrow + gid + 8) * HSTR + kk + 8 + 2 * tig];
            #pragma unroll
            for (int nt = 0; nt < 8; nt++) {
                unsigned int b0 = *(const unsigned int*)&Ks[(nt * 8 + gid) * HSTR + kk + 2 * tig];
                unsigned int b1 = *(const unsigned int*)&Ks[(nt * 8 + gid) * HSTR + kk + 8 + 2 * tig];
                mma_f16(s[nt], a, b0, b1);
            }
        }

        const bool need_mask = (jt * 64 + 63 > rowbase + mrow);
        #pragma unroll
        for (int nt = 0; nt < 8; nt++) {
            int col = jt * 64 + nt * 8 + tig * 2;
            if (need_mask) {
                s[nt][0] = (col     <= row0) ? s[nt][0] * sscale : -1e30f;
                s[nt][1] = (col + 1 <= row0) ? s[nt][1] * sscale : -1e30f;
                s[nt][2] = (col     <= row1) ? s[nt][2] * sscale : -1e30f;
                s[nt][3] = (col + 1 <= row1) ? s[nt][3] * sscale : -1e30f;
            } else {
                s[nt][0] *= sscale; s[nt][1] *= sscale;
                s[nt][2] *= sscale; s[nt][3] *= sscale;
            }
        }

        float tm0 = -1e30f, tm1 = -1e30f;
        #pragma unroll
        for (int nt = 0; nt < 8; nt++) {
            tm0 = fmaxf(tm0, fmaxf(s[nt][0], s[nt][1]));
            tm1 = fmaxf(tm1, fmaxf(s[nt][2], s[nt][3]));
        }
        tm0 = fmaxf(tm0, __shfl_xor_sync(0xffffffffu, tm0, 1));
        tm0 = fmaxf(tm0, __shfl_xor_sync(0xffffffffu, tm0, 2));
        tm1 = fmaxf(tm1, __shfl_xor_sync(0xffffffffu, tm1, 1));
        tm1 = fmaxf(tm1, __shfl_xor_sync(0xffffffffu, tm1, 2));

        float mn0 = fmaxf(m0, tm0);
        float mn1 = fmaxf(m1, tm1);
        float corr0 = exp2f(m0 - mn0);
        float corr1 = exp2f(m1 - mn1);

        float rs0 = 0.f, rs1 = 0.f;
        #pragma unroll
        for (int nt = 0; nt < 8; nt++) {
            float p00 = exp2f(s[nt][0] - mn0);
            float p01 = exp2f(s[nt][1] - mn0);
            float p10 = exp2f(s[nt][2] - mn1);
            float p11 = exp2f(s[nt][3] - mn1);
            rs0 += p00 + p01;
            rs1 += p10 + p11;
            *(__half2*)&Ps[(mrow + gid    ) * HSTR + nt * 8 + tig * 2] = __floats2half2_rn(p00, p01);
            *(__half2*)&Ps[(mrow + gid + 8) * HSTR + nt * 8 + tig * 2] = __floats2half2_rn(p10, p11);
        }
        rs0 += __shfl_xor_sync(0xffffffffu, rs0, 1);
        rs0 += __shfl_xor_sync(0xffffffffu, rs0, 2);
        rs1 += __shfl_xor_sync(0xffffffffu, rs1, 1);
        rs1 += __shfl_xor_sync(0xffffffffu, rs1, 2);

        l0 = l0 * corr0 + rs0;  m0 = mn0;
        l1 = l1 * corr1 + rs1;  m1 = mn1;
        #pragma unroll
        for (int nt = 0; nt < 8; nt++) {
            o_[nt][0] *= corr0; o_[nt][1] *= corr0;
            o_[nt][2] *= corr1; o_[nt][3] *= corr1;
        }
        __syncwarp();

        // O += P V  (A = Ps rows, B = Vt [dim][token])
        #pragma unroll
        for (int kk = 0; kk < 64; kk += 16) {
            unsigned int a[4];
            a[0] = *(const unsigned int*)&Ps[(mrow + gid    ) * HSTR + kk + 2 * tig];
            a[1] = *(const unsigned int*)&Ps[(mrow + gid + 8) * HSTR + kk + 2 * tig];
            a[2] = *(const unsigned int*)&Ps[(mrow + gid    ) * HSTR + kk + 8 + 2 * tig];
            a[3] = *(const unsigned int*)&Ps[(mrow + gid + 8) * HSTR + kk + 8 + 2 * tig];
            #pragma unroll
            for (int nt = 0; nt < 8; nt++) {
                unsigned int b0 = *(const unsigned int*)&Vt[(nt * 8 + gid) * HSTR + kk + 2 * tig];
                unsigned int b1 = *(const unsigned int*)&Vt[(nt * 8 + gid) * HSTR + kk + 8 + 2 * tig];
                mma_f16(o_[nt], a, b0, b1);
            }
        }
    }

    float inv0 = 1.f / l0;
    float inv1 = 1.f / l1;
    #pragma unroll
    for (int nt = 0; nt < 8; nt++) {
        int c = h * 64 + nt * 8 + tig * 2;
        *(__half2*)&obuf[(long)(b * TT + row0) * DD + c] =
            __floats2half2_rn(o_[nt][0] * inv0, o_[nt][1] * inv0);
        *(__half2*)&obuf[(long)(b * TT + row1) * DD + c] =
            __floats2half2_rn(o_[nt][2] * inv1, o_[nt][3] * inv1);
    }
}

// ---------------------------------------------------------------------------
// out = x + LayerNorm(y)*g + be ; writes f32 (outf) or half (outh).
// ---------------------------------------------------------------------------
__global__ __launch_bounds__(256) void ln_kernel(
    const float* __restrict__ x, const float* __restrict__ y,
    const float* __restrict__ g, const float* __restrict__ be,
    float* __restrict__ outf, __half* __restrict__ outh)
{
    int row = blockIdx.x;
    int tid = threadIdx.x;
    float4 v = ((const float4*)(y + (long)row * DD))[tid];
    float s  = v.x + v.y + v.z + v.w;
    float ss = v.x * v.x + v.y * v.y + v.z * v.z + v.w * v.w;
    #pragma unroll
    for (int off = 16; off >= 1; off >>= 1) {
        s  += __shfl_xor_sync(0xffffffffu, s,  off);
        ss += __shfl_xor_sync(0xffffffffu, ss, off);
    }
    __shared__ float sb[8], ssb[8];
    if ((tid & 31) == 0) { sb[tid >> 5] = s; ssb[tid >> 5] = ss; }
    __syncthreads();
    float tot = 0.f, tots = 0.f;
    #pragma unroll
    for (int w = 0; w < 8; w++) { tot += sb[w]; tots += ssb[w]; }
    float mu = tot * (1.f / 1024.f);
    float var = tots * (1.f / 1024.f) - mu * mu;
    float rstd = rsqrtf(var + 1e-5f);

    float4 xv = ((const float4*)(x + (long)row * DD))[tid];
    float4 gv = ((const float4*)g)[tid];
    float4 bv = ((const float4*)be)[tid];
    float4 o;
    o.x = xv.x + (v.x - mu) * rstd * gv.x + bv.x;
    o.y = xv.y + (v.y - mu) * rstd * gv.y + bv.y;
    o.z = xv.z + (v.z - mu) * rstd * gv.z + bv.z;
    o.w = xv.w + (v.w - mu) * rstd * gv.w + bv.w;
    if (outh) {
        __half2 h0 = __floats2half2_rn(o.x, o.y);
        __half2 h1 = __floats2half2_rn(o.z, o.w);
        *(__half2*)&outh[(long)row * DD + tid * 4]     = h0;
        *(__half2*)&outh[(long)row * DD + tid * 4 + 2] = h1;
    } else {
        ((float4*)(outf + (long)row * DD))[tid] = o;
    }
}

// ---------------------------------------------------------------------------
// launch
// ---------------------------------------------------------------------------
extern "C" void kernel_launch(void* const* d_in, const int* in_sizes, int n_in,
                              void* d_out, int out_size)
{
    const float* x   = (const float*)d_in[0];
    const float* Wq  = (const float*)d_in[1];
    const float* Wk  = (const float*)d_in[2];
    const float* Wv  = (const float*)d_in[3];
    const float* Wo  = (const float*)d_in[4];
    const float* bo  = (const float*)d_in[5];
    const float* W1  = (const float*)d_in[6];
    const float* b1  = (const float*)d_in[7];
    const float* W2  = (const float*)d_in[8];
    const float* b2  = (const float*)d_in[9];
    const float* g1  = (const float*)d_in[10];
    const float* be1 = (const float*)d_in[11];
    const float* g2  = (const float*)d_in[12];
    const float* be2 = (const float*)d_in[13];
    float* out = (float*)d_out;

    __half *packedWT, *xh, *WoT, *W1T, *W2T, *qkv, *obuf, *abuf, *h1;
    float *t1;
    cudaGetSymbolAddress((void**)&packedWT, g_packedWT);
    cudaGetSymbolAddress((void**)&xh,       g_xh);
    cudaGetSymbolAddress((void**)&WoT,      g_WoT);
    cudaGetSymbolAddress((void**)&W1T,      g_W1T);
    cudaGetSymbolAddress((void**)&W2T,      g_W2T);
    cudaGetSymbolAddress((void**)&qkv,      g_qkv);
    cudaGetSymbolAddress((void**)&obuf,     g_obuf);
    cudaGetSymbolAddress((void**)&abuf,     g_abuf);
    cudaGetSymbolAddress((void**)&h1,       g_h1);
    cudaGetSymbolAddress((void**)&t1,       g_t1);

    cudaFuncSetAttribute(attn_h_kernel,
                         cudaFuncAttributeMaxDynamicSharedMemorySize, ATTN_SMEM_BYTES);
    cudaFuncSetAttribute(hgemm_kernel,
                         cudaFuncAttributeMaxDynamicSharedMemorySize, HGEMM_SMEM);

    // 0) prep: convert x; transpose+convert all weights to [N][K] half
    tohalf_kernel<<<(MROWS * DD) / 2048, 256>>>(x, xh);
    transpose_qkv_kernel<<<dim3(2, 32, 48), 256>>>(Wq, Wk, Wv, packedWT);
    transpose_kernel<<<dim3(DD / 32, DD / 32), 256>>>(Wo, DD, DD, WoT);
    transpose_kernel<<<dim3(FF / 32, DD / 32), 256>>>(W1, DD, FF, W1T);
    transpose_kernel<<<dim3(DD / 32, FF / 32), 256>>>(W2, FF, DD, W2T);

    // 1) qkv = xh @ packedW   [4096,1024]x[1024,3072] -> half
    hgemm_kernel<<<dim3(3 * DD / 128, MROWS / 128), 256, HGEMM_SMEM>>>(
        xh, DD, packedWT, DD, nullptr, qkv, 3 * DD, nullptr, 0);

    // 2) attention -> half obuf
    attn_h_kernel<<<dim3(TT / 128, HH, BB), 256, ATTN_SMEM_BYTES>>>(qkv, obuf);

    // 3) attn_out = obuf @ Wo + bo -> f32 t1
    hgemm_kernel<<<dim3(DD / 128, MROWS / 128), 256, HGEMM_SMEM>>>(
        obuf, DD, WoT, DD, t1, nullptr, DD, bo, 0);

    // 4) a = x + LN(attn_out) -> half abuf
    ln_kernel<<<MROWS, 256>>>(x, t1, g1, be1, nullptr, abuf);

    // 5) h1 = relu(a @ W1 + b1) -> half
    hgemm_kernel<<<dim3(FF / 128, MROWS / 128), 256, HGEMM_SMEM>>>(
        abuf, DD, W1T, DD, nullptr, h1, FF, b1, 1);

    // 6) f = h1 @ W2 + b2 -> f32 t1
    hgemm_kernel<<<dim3(DD / 128, MROWS / 128), 256, HGEMM_SMEM>>>(
        h1, FF, W2T, FF, t1, nullptr, DD, b2, 0);

    // 7) out = x + LN(f)
    ln_kernel<<<MROWS, 256>>>(x, t1, g2, be2, out, nullptr);
}

// round 11
// speedup vs baseline: 6.5723x; 1.0283x over previous
#include <cuda_runtime.h>
#include <cuda_fp16.h>
#include <stdint.h>

// Problem constants
#define BB 2
#define TT 2048
#define DD 1024
#define HH 16
#define DHH 64
#define FF 4096
#define MROWS (BB*TT)   // 4096

// ---------------------------------------------------------------------------
// Scratch (device globals; no allocations allowed)
// ---------------------------------------------------------------------------
__device__ __align__(16) __half g_packedWT[3 * DD * DD]; // [3072][1024] K-major
__device__ __align__(16) __half g_xh[MROWS * DD];        // half x
__device__ __align__(16) __half g_WoT[DD * DD];          // [1024][1024] K-major
__device__ __align__(16) __half g_W1T[FF * DD];          // [4096][1024] K-major
__device__ __align__(16) __half g_W2T[DD * FF];          // [1024][4096] K-major
__device__ __align__(16) __half g_qkv[MROWS * 3 * DD];   // [4096][3072]
__device__ __align__(16) __half g_obuf[MROWS * DD];      // attention out
__device__ __align__(16) __half g_abuf[MROWS * DD];      // a (half)
__device__ __align__(16) __half g_h1[MROWS * FF];        // relu(a@W1+b1)
__device__ float g_t1[MROWS * DD];                       // f32 LN inputs

__device__ __forceinline__ void cp_async16(unsigned int s, const void* g) {
    asm volatile("cp.async.cg.shared.global [%0], [%1], 16;\n" :: "r"(s), "l"(g));
}

__device__ __forceinline__ void mma_f16(float* c, const unsigned int* a,
                                        unsigned int b0, unsigned int b1) {
    asm volatile(
        "mma.sync.aligned.m16n8k16.row.col.f32.f16.f16.f32 "
        "{%0,%1,%2,%3},{%4,%5,%6,%7},{%8,%9},{%0,%1,%2,%3};\n"
        : "+f"(c[0]), "+f"(c[1]), "+f"(c[2]), "+f"(c[3])
        : "r"(a[0]), "r"(a[1]), "r"(a[2]), "r"(a[3]), "r"(b0), "r"(b1));
}

__device__ __forceinline__ void ldsm4(unsigned int& r0, unsigned int& r1,
                                      unsigned int& r2, unsigned int& r3,
                                      unsigned int addr) {
    asm volatile("ldmatrix.sync.aligned.m8n8.x4.shared.b16 {%0,%1,%2,%3}, [%4];"
                 : "=r"(r0), "=r"(r1), "=r"(r2), "=r"(r3) : "r"(addr));
}

// exp2 on the FMA pipe: round-to-int bit trick + degree-4 Taylor on [-0.5,0.5].
// Valid for x <= 0 (clamped at -30). Max rel err ~4e-5.
__device__ __forceinline__ float fast_exp2(float x) {
    x = fmaxf(x, -30.f);
    float t = x + 12582912.f;                       // 1.5*2^23: round to int
    int ni = __float_as_int(t) - 0x4B400000;        // integer part
    float f = x - (t - 12582912.f);                 // frac in [-0.5, 0.5]
    float p = 0.00961813f;
    p = fmaf(p, f, 0.0555041f);
    p = fmaf(p, f, 0.240227f);
    p = fmaf(p, f, 0.693147f);
    p = fmaf(p, f, 1.0f);
    return p * __int_as_float((ni + 127) << 23);
}

// ---------------------------------------------------------------------------
// f32 -> half conversion, 8 elements/thread
// ---------------------------------------------------------------------------
__global__ __launch_bounds__(256) void tohalf_kernel(
    const float* __restrict__ in, __half* __restrict__ out)
{
    int i = blockIdx.x * 256 + threadIdx.x;
    float4 v0 = ((const float4*)in)[2 * i];
    float4 v1 = ((const float4*)in)[2 * i + 1];
    __half2 h[4];
    h[0] = __floats2half2_rn(v0.x, v0.y);
    h[1] = __floats2half2_rn(v0.z, v0.w);
    h[2] = __floats2half2_rn(v1.x, v1.y);
    h[3] = __floats2half2_rn(v1.z, v1.w);
    *(uint4*)&out[i * 8] = *(uint4*)h;
}

// ---------------------------------------------------------------------------
// Tiled transpose + half convert: dst[c][r] = half(src[r][c]).
// ---------------------------------------------------------------------------
__global__ __launch_bounds__(256) void transpose_kernel(
    const float* __restrict__ src, int rows, int cols, __half* __restrict__ dst)
{
    __shared__ float t[32][33];
    int bx = blockIdx.x * 32, by = blockIdx.y * 32;
    int tx = threadIdx.x & 31, ty = threadIdx.x >> 5;
    #pragma unroll
    for (int i = 0; i < 4; i++)
        t[ty + i * 8][tx] = src[(long)(by + ty + i * 8) * cols + bx + tx];
    __syncthreads();
    #pragma unroll
    for (int i = 0; i < 4; i++)
        dst[(long)(bx + ty + i * 8) * rows + by + tx] = __float2half(t[tx][ty + i * 8]);
}

// ---------------------------------------------------------------------------
// QKV weight transpose: Wq/Wk/Wv (H,D,DH) -> packedWT [3072][1024] K-major half.
// ---------------------------------------------------------------------------
__global__ __launch_bounds__(256) void transpose_qkv_kernel(
    const float* __restrict__ Wq, const float* __restrict__ Wk,
    const float* __restrict__ Wv, __half* __restrict__ dst)
{
    __shared__ float t[32][33];
    int z = blockIdx.z;
    int w = z >> 4, h = z & 15;
    const float* src = ((w == 0) ? Wq : (w == 1) ? Wk : Wv) + (long)h * (DD * DHH);
    int bx = blockIdx.x * 32, by = blockIdx.y * 32;
    int tx = threadIdx.x & 31, ty = threadIdx.x >> 5;
    #pragma unroll
    for (int i = 0; i < 4; i++)
        t[ty + i * 8][tx] = src[(long)(by + ty + i * 8) * DHH + bx + tx];
    __syncthreads();
    #pragma unroll
    for (int i = 0; i < 4; i++)
        dst[(long)(w * 1024 + h * 64 + bx + ty + i * 8) * DD + by + tx] =
            __float2half(t[tx][ty + i * 8]);
}

// ---------------------------------------------------------------------------
// fp16 tensor-core GEMM with ldmatrix fragment loads.
// C = A[M,K] * BT[N,K]^T (+bias)(+relu); 128x128 tile, K-chunk 64, 2-stage.
// ---------------------------------------------------------------------------
#define HSTR 72                           // halves per smem row (64 + 8 pad)
#define HSTAGE_B (128 * HSTR * 2 * 2)     // A + B per stage = 36864 bytes
#define HGEMM_SMEM (2 * HSTAGE_B)         // 73728

__global__ __launch_bounds__(256, 2) void hgemm_kernel(
    const __half* __restrict__ A, int lda,
    const __half* __restrict__ BT, int K,
    float* __restrict__ Cf, __half* __restrict__ Ch, int ldc,
    const float* __restrict__ bias, int do_relu)
{
    extern __shared__ __align__(16) char dsm[];
    const int tid  = threadIdx.x;
    const int lane = tid & 31;
    const int warp = tid >> 5;
    const int gid  = lane >> 2;
    const int tig  = lane & 3;
    const int wm   = warp & 1;
    const int wn   = warp >> 1;
    const int rowBase = blockIdx.y * 128;
    const int colBase = blockIdx.x * 128;
    const unsigned int smem_u = (unsigned int)__cvta_generic_to_shared(dsm);

    // per-lane ldmatrix row offsets (bytes, within stage)
    const unsigned int aOff = ((wm * 64 + (lane & 15)) * HSTR + ((lane & 16) >> 1)) * 2;
    const unsigned int bRow = wn * 32 + (lane & 7) + ((lane >> 1) & 8);
    const unsigned int bOff = 128 * HSTR * 2 + (bRow * HSTR + (lane & 8)) * 2;

    float acc[16][4];
    #pragma unroll
    for (int i = 0; i < 16; i++)
        #pragma unroll
        for (int j = 0; j < 4; j++) acc[i][j] = 0.f;

    auto issue = [&](int stage, int k0) {
        unsigned int st = smem_u + stage * HSTAGE_B;
        #pragma unroll
        for (int p = 0; p < 4; p++) {            // A: 128 rows x 8 x 16B
            int i = tid + p * 256;
            int r = i >> 3, q = i & 7;
            cp_async16(st + r * (HSTR * 2) + q * 16,
                       A + (long)(rowBase + r) * lda + k0 + q * 8);
        }
        #pragma unroll
        for (int p = 0; p < 4; p++) {            // B: 128 n-rows x 8 x 16B
            int i = tid + p * 256;
            int n = i >> 3, q = i & 7;
            cp_async16(st + 128 * (HSTR * 2) + n * (HSTR * 2) + q * 16,
                       BT + (long)(colBase + n) * K + k0 + q * 8);
        }
        asm volatile("cp.async.commit_group;\n");
    };

    issue(0, 0);
    const int nk = K / 64;

    for (int kt = 0; kt < nk; kt++) {
        if (kt + 1 < nk) {
            issue((kt + 1) & 1, (kt + 1) * 64);
            asm volatile("cp.async.wait_group 1;\n");
        } else {
            asm volatile("cp.async.wait_group 0;\n");
        }
        __syncthreads();

        const unsigned int st = smem_u + (kt & 1) * HSTAGE_B;

        #pragma unroll
        for (int ks = 0; ks < 4; ks++) {
            const int kkb = ks * 16 * 2;        // byte offset of k-chunk
            unsigned int a[4][4], b[2][4];
            #pragma unroll
            for (int mt = 0; mt < 4; mt++)
                ldsm4(a[mt][0], a[mt][1], a[mt][2], a[mt][3],
                      st + aOff + mt * 16 * HSTR * 2 + kkb);
            #pragma unroll
            for (int pr = 0; pr < 2; pr++)       // pair pr covers nt=2pr,2pr+1
                ldsm4(b[pr][0], b[pr][1], b[pr][2], b[pr][3],
                      st + bOff + pr * 16 * HSTR * 2 + kkb);
            #pragma unroll
            for (int mt = 0; mt < 4; mt++) {
                mma_f16(acc[mt * 4 + 0], a[mt], b[0][0], b[0][1]);
                mma_f16(acc[mt * 4 + 1], a[mt], b[0][2], b[0][3]);
                mma_f16(acc[mt * 4 + 2], a[mt], b[1][0], b[1][1]);
                mma_f16(acc[mt * 4 + 3], a[mt], b[1][2], b[1][3]);
            }
        }
        __syncthreads();
    }

    // epilogue
    #pragma unroll
    for (int mt = 0; mt < 4; mt++) {
        int r0 = rowBase + wm * 64 + mt * 16 + gid;
        #pragma unroll
        for (int nt = 0; nt < 4; nt++) {
            int c = colBase + wn * 32 + nt * 8 + tig * 2;
            float* v = acc[mt * 4 + nt];
            float o0 = v[0], o1 = v[1], o2 = v[2], o3 = v[3];
            if (bias) {
                float b0 = bias[c], b1 = bias[c + 1];
                o0 += b0; o1 += b1; o2 += b0; o3 += b1;
            }
            if (do_relu) {
                o0 = fmaxf(o0, 0.f); o1 = fmaxf(o1, 0.f);
                o2 = fmaxf(o2, 0.f); o3 = fmaxf(o3, 0.f);
            }
            if (Ch) {
                *(__half2*)&Ch[(long)r0 * ldc + c]       = __floats2half2_rn(o0, o1);
                *(__half2*)&Ch[(long)(r0 + 8) * ldc + c] = __floats2half2_rn(o2, o3);
            } else {
                *(float2*)&Cf[(long)r0 * ldc + c]       = make_float2(o0, o1);
                *(float2*)&Cf[(long)(r0 + 8) * ldc + c] = make_float2(o2, o3);
            }
        }
    }
}

// ---------------------------------------------------------------------------
// fp16 tensor-core causal flash attention (ldmatrix + FMA-pipe exp2).
// 256 threads (8 warps), Q tile 128 rows, warp owns 16 rows, K tile 64.
// ---------------------------------------------------------------------------
#define ATTN_SMEM_BYTES ((128 + 64 + 64 + 128) * HSTR * 2)   // 55296

__global__ __launch_bounds__(256) void attn_h_kernel(
    const __half* __restrict__ qkv, __half* __restrict__ obuf)
{
    extern __shared__ __align__(16) __half hsm[];
    __half* Qs = hsm;                   // [128][HSTR]
    __half* Ks = Qs + 128 * HSTR;       // [64][HSTR]  K natural [token][dim]
    __half* Vt = Ks + 64 * HSTR;        // [64][HSTR]  V transposed [dim][token]
    __half* Ps = Vt + 64 * HSTR;        // [128][HSTR]

    const int tid  = threadIdx.x;
    const int lane = tid & 31;
    const int warp = tid >> 5;
    const int gid  = lane >> 2;
    const int tig  = lane & 3;
    const int iq   = (int)gridDim.x - 1 - (int)blockIdx.x;
    const int h    = blockIdx.y;
    const int b    = blockIdx.z;
    const int rowbase = iq * 128;
    const int mrow = warp * 16;
    const long base = (long)b * TT * 3072;

    const unsigned int qs_u = (unsigned int)__cvta_generic_to_shared(Qs);
    const unsigned int ks_u = (unsigned int)__cvta_generic_to_shared(Ks);
    const unsigned int vt_u = (unsigned int)__cvta_generic_to_shared(Vt);
    const unsigned int ps_u = (unsigned int)__cvta_generic_to_shared(Ps);

    // ldmatrix per-lane offsets (bytes)
    const unsigned int aOffQ = ((mrow + (lane & 15)) * HSTR + ((lane & 16) >> 1)) * 2;
    const unsigned int bRowK = (lane & 7) + ((lane >> 1) & 8);
    const unsigned int bOffK = (bRowK * HSTR + (lane & 8)) * 2;

    // Load Q tile [128][64] halves
    {
        int r  = tid >> 1;
        int dg = (tid & 1) * 32;
        const __half* qp = qkv + base + (long)(rowbase + r) * 3072 + h * 64 + dg;
        #pragma unroll
        for (int it = 0; it < 4; it++)
            *(uint4*)&Qs[r * HSTR + dg + it * 8] = *(const uint4*)(qp + it * 8);
    }

    const float sscale = 0.125f * 1.44269504f;
    float m0 = -1e30f, m1 = -1e30f, l0 = 0.f, l1 = 0.f;
    float o_[8][4];
    #pragma unroll
    for (int nt = 0; nt < 8; nt++)
        #pragma unroll
        for (int j = 0; j < 4; j++) o_[nt][j] = 0.f;

    const int row0 = rowbase + mrow + gid;
    const int row1 = row0 + 8;
    const int jmax = (rowbase >> 6) + 1;

    for (int jt = 0; jt <= jmax; jt++) {
        __syncthreads();
        // Load K (natural) and V (transposed)
        {
            int r  = tid >> 2;          // token 0..63
            int dg = (tid & 3) * 16;    // dim chunk
            const __half* kp = qkv + base + (long)(jt * 64 + r) * 3072 + 1024 + h * 64 + dg;
            const __half* vp = kp + 1024;
            #pragma unroll
            for (int it = 0; it < 2; it++)
                *(uint4*)&Ks[r * HSTR + dg + it * 8] = *(const uint4*)(kp + it * 8);
            #pragma unroll
            for (int it = 0; it < 2; it++) {
                uint4 raw = *(const uint4*)(vp + it * 8);
                __half tmp[8];
                *(uint4*)tmp = raw;
                #pragma unroll
                for (int j = 0; j < 8; j++)
                    Vt[(dg + it * 8 + j) * HSTR + r] = tmp[j];
            }
        }
        __syncthreads();

        if (jt * 64 > rowbase + mrow + 15) continue;

        // S = Q K^T
        float s[8][4];
        #pragma unroll
        for (int nt = 0; nt < 8; nt++)
            #pragma unroll
            for (int j = 0; j < 4; j++) s[nt][j] = 0.f;

        #pragma unroll
        for (int kk = 0; kk < 64; kk += 16) {
            unsigned int a[4], bk[4][4];
            ldsm4(a[0], a[1], a[2], a[3], qs_u + aOffQ + kk * 2);
            #pragma unroll
            for (int pr = 0; pr < 4; pr++)
                ldsm4(bk[pr][0], bk[pr][1], bk[pr][2], bk[pr][3],
                      ks_u + bOffK + pr * 16 * HSTR * 2 + kk * 2);
            #pragma unroll
            for (int pr = 0; pr < 4; pr++) {
                mma_f16(s[pr * 2 + 0], a, bk[pr][0], bk[pr][1]);
                mma_f16(s[pr * 2 + 1], a, bk[pr][2], bk[pr][3]);
            }
        }

        const bool need_mask = (jt * 64 + 63 > rowbase + mrow);
        #pragma unroll
        for (int nt = 0; nt < 8; nt++) {
            int col = jt * 64 + nt * 8 + tig * 2;
            if (need_mask) {
                s[nt][0] = (col     <= row0) ? s[nt][0] * sscale : -1e30f;
                s[nt][1] = (col + 1 <= row0) ? s[nt][1] * sscale : -1e30f;
                s[nt][2] = (col     <= row1) ? s[nt][2] * sscale : -1e30f;
                s[nt][3] = (col + 1 <= row1) ? s[nt][3] * sscale : -1e30f;
            } else {
                s[nt][0] *= sscale; s[nt][1] *= sscale;
                s[nt][2] *= sscale; s[nt][3] *= sscale;
            }
        }

        float tm0 = -1e30f, tm1 = -1e30f;
        #pragma unroll
        for (int nt = 0; nt < 8; nt++) {
            tm0 = fmaxf(tm0, fmaxf(s[nt][0], s[nt][1]));
            tm1 = fmaxf(tm1, fmaxf(s[nt][2], s[nt][3]));
        }
        tm0 = fmaxf(tm0, __shfl_xor_sync(0xffffffffu, tm0, 1));
        tm0 = fmaxf(tm0, __shfl_xor_sync(0xffffffffu, tm0, 2));
        tm1 = fmaxf(tm1, __shfl_xor_sync(0xffffffffu, tm1, 1));
        tm1 = fmaxf(tm1, __shfl_xor_sync(0xffffffffu, tm1, 2));

        float mn0 = fmaxf(m0, tm0);
        float mn1 = fmaxf(m1, tm1);
        float corr0 = fast_exp2(m0 - mn0);
        float corr1 = fast_exp2(m1 - mn1);

        float rs0 = 0.f, rs1 = 0.f;
        #pragma unroll
        for (int nt = 0; nt < 8; nt++) {
            float p00 = fast_exp2(s[nt][0] - mn0);
            float p01 = fast_exp2(s[nt][1] - mn0);
            float p10 = fast_exp2(s[nt][2] - mn1);
            float p11 = fast_exp2(s[nt][3] - mn1);
            rs0 += p00 + p01;
            rs1 += p10 + p11;
            *(__half2*)&Ps[(mrow + gid    ) * HSTR + nt * 8 + tig * 2] = __floats2half2_rn(p00, p01);
            *(__half2*)&Ps[(mrow + gid + 8) * HSTR + nt * 8 + tig * 2] = __floats2half2_rn(p10, p11);
        }
        rs0 += __shfl_xor_sync(0xffffffffu, rs0, 1);
        rs0 += __shfl_xor_sync(0xffffffffu, rs0, 2);
        rs1 += __shfl_xor_sync(0xffffffffu, rs1, 1);
        rs1 += __shfl_xor_sync(0xffffffffu, rs1, 2);

        l0 = l0 * corr0 + rs0;  m0 = mn0;
        l1 = l1 * corr1 + rs1;  m1 = mn1;
        #pragma unroll
        for (int nt = 0; nt < 8; nt++) {
            o_[nt][0] *= corr0; o_[nt][1] *= corr0;
            o_[nt][2] *= corr1; o_[nt][3] *= corr1;
        }
        __syncwarp();

        // O += P V
        #pragma unroll
        for (int kk = 0; kk < 64; kk += 16) {
            unsigned int a[4], bv[4][4];
            ldsm4(a[0], a[1], a[2], a[3], ps_u + aOffQ + kk * 2);
            #pragma unroll
            for (int pr = 0; pr < 4; pr++)
                ldsm4(bv[pr][0], bv[pr][1], bv[pr][2], bv[pr][3],
                      vt_u + bOffK + pr * 16 * HSTR * 2 + kk * 2);
            #pragma unroll
            for (int pr = 0; pr < 4; pr++) {
                mma_f16(o_[pr * 2 + 0], a, bv[pr][0], bv[pr][1]);
                mma_f16(o_[pr * 2 + 1], a, bv[pr][2], bv[pr][3]);
            }
        }
    }

    float inv0 = 1.f / l0;
    float inv1 = 1.f / l1;
    #pragma unroll
    for (int nt = 0; nt < 8; nt++) {
        int c = h * 64 + nt * 8 + tig * 2;
        *(__half2*)&obuf[(long)(b * TT + row0) * DD + c] =
            __floats2half2_rn(o_[nt][0] * inv0, o_[nt][1] * inv0);
        *(__half2*)&obuf[(long)(b * TT + row1) * DD + c] =
            __floats2half2_rn(o_[nt][2] * inv1, o_[nt][3] * inv1);
    }
}

// ---------------------------------------------------------------------------
// out = x + LayerNorm(y)*g + be ; writes f32 (outf) or half (outh).
// ---------------------------------------------------------------------------
__global__ __launch_bounds__(256) void ln_kernel(
    const float* __restrict__ x, const float* __restrict__ y,
    const float* __restrict__ g, const float* __restrict__ be,
    float* __restrict__ outf, __half* __restrict__ outh)
{
    int row = blockIdx.x;
    int tid = threadIdx.x;
    float4 v = ((const float4*)(y + (long)row * DD))[tid];
    float s  = v.x + v.y + v.z + v.w;
    float ss = v.x * v.x + v.y * v.y + v.z * v.z + v.w * v.w;
    #pragma unroll
    for (int off = 16; off >= 1; off >>= 1) {
        s  += __shfl_xor_sync(0xffffffffu, s,  off);
        ss += __shfl_xor_sync(0xffffffffu, ss, off);
    }
    __shared__ float sb[8], ssb[8];
    if ((tid & 31) == 0) { sb[tid >> 5] = s; ssb[tid >> 5] = ss; }
    __syncthreads();
    float tot = 0.f, tots = 0.f;
    #pragma unroll
    for (int w = 0; w < 8; w++) { tot += sb[w]; tots += ssb[w]; }
    float mu = tot * (1.f / 1024.f);
    float var = tots * (1.f / 1024.f) - mu * mu;
    float rstd = rsqrtf(var + 1e-5f);

    float4 xv = ((const float4*)(x + (long)row * DD))[tid];
    float4 gv = ((const float4*)g)[tid];
    float4 bv = ((const float4*)be)[tid];
    float4 o;
    o.x = xv.x + (v.x - mu) * rstd * gv.x + bv.x;
    o.y = xv.y + (v.y - mu) * rstd * gv.y + bv.y;
    o.z = xv.z + (v.z - mu) * rstd * gv.z + bv.z;
    o.w = xv.w + (v.w - mu) * rstd * gv.w + bv.w;
    if (outh) {
        __half2 h0 = __floats2half2_rn(o.x, o.y);
        __half2 h1 = __floats2half2_rn(o.z, o.w);
        *(__half2*)&outh[(long)row * DD + tid * 4]     = h0;
        *(__half2*)&outh[(long)row * DD + tid * 4 + 2] = h1;
    } else {
        ((float4*)(outf + (long)row * DD))[tid] = o;
    }
}

// ---------------------------------------------------------------------------
// launch
// ---------------------------------------------------------------------------
extern "C" void kernel_launch(void* const* d_in, const int* in_sizes, int n_in,
                              void* d_out, int out_size)
{
    const float* x   = (const float*)d_in[0];
    const float* Wq  = (const float*)d_in[1];
    const float* Wk  = (const float*)d_in[2];
    const float* Wv  = (const float*)d_in[3];
    const float* Wo  = (const float*)d_in[4];
    const float* bo  = (const float*)d_in[5];
    const float* W1  = (const float*)d_in[6];
    const float* b1  = (const float*)d_in[7];
    const float* W2  = (const float*)d_in[8];
    const float* b2  = (const float*)d_in[9];
    const float* g1  = (const float*)d_in[10];
    const float* be1 = (const float*)d_in[11];
    const float* g2  = (const float*)d_in[12];
    const float* be2 = (const float*)d_in[13];
    float* out = (float*)d_out;

    __half *packedWT, *xh, *WoT, *W1T, *W2T, *qkv, *obuf, *abuf, *h1;
    float *t1;
    cudaGetSymbolAddress((void**)&packedWT, g_packedWT);
    cudaGetSymbolAddress((void**)&xh,       g_xh);
    cudaGetSymbolAddress((void**)&WoT,      g_WoT);
    cudaGetSymbolAddress((void**)&W1T,      g_W1T);
    cudaGetSymbolAddress((void**)&W2T,      g_W2T);
    cudaGetSymbolAddress((void**)&qkv,      g_qkv);
    cudaGetSymbolAddress((void**)&obuf,     g_obuf);
    cudaGetSymbolAddress((void**)&abuf,     g_abuf);
    cudaGetSymbolAddress((void**)&h1,       g_h1);
    cudaGetSymbolAddress((void**)&t1,       g_t1);

    cudaFuncSetAttribute(attn_h_kernel,
                         cudaFuncAttributeMaxDynamicSharedMemorySize, ATTN_SMEM_BYTES);
    cudaFuncSetAttribute(hgemm_kernel,
                         cudaFuncAttributeMaxDynamicSharedMemorySize, HGEMM_SMEM);

    // 0) prep: convert x; transpose+convert all weights to [N][K] half
    tohalf_kernel<<<(MROWS * DD) / 2048, 256>>>(x, xh);
    transpose_qkv_kernel<<<dim3(2, 32, 48), 256>>>(Wq, Wk, Wv, packedWT);
    transpose_kernel<<<dim3(DD / 32, DD / 32), 256>>>(Wo, DD, DD, WoT);
    transpose_kernel<<<dim3(FF / 32, DD / 32), 256>>>(W1, DD, FF, W1T);
    transpose_kernel<<<dim3(DD / 32, FF / 32), 256>>>(W2, FF, DD, W2T);

    // 1) qkv = xh @ packedW -> half
    hgemm_kernel<<<dim3(3 * DD / 128, MROWS / 128), 256, HGEMM_SMEM>>>(
        xh, DD, packedWT, DD, nullptr, qkv, 3 * DD, nullptr, 0);

    // 2) attention -> half obuf
    attn_h_kernel<<<dim3(TT / 128, HH, BB), 256, ATTN_SMEM_BYTES>>>(qkv, obuf);

    // 3) attn_out = obuf @ Wo + bo -> f32 t1
    hgemm_kernel<<<dim3(DD / 128, MROWS / 128), 256, HGEMM_SMEM>>>(
        obuf, DD, WoT, DD, t1, nullptr, DD, bo, 0);

    // 4) a = x + LN(attn_out) -> half abuf
    ln_kernel<<<MROWS, 256>>>(x, t1, g1, be1, nullptr, abuf);

    // 5) h1 = relu(a @ W1 + b1) -> half
    hgemm_kernel<<<dim3(FF / 128, MROWS / 128), 256, HGEMM_SMEM>>>(
        abuf, DD, W1T, DD, nullptr, h1, FF, b1, 1);

    // 6) f = h1 @ W2 + b2 -> f32 t1
    hgemm_kernel<<<dim3(DD / 128, MROWS / 128), 256, HGEMM_SMEM>>>(
        h1, FF, W2T, FF, t1, nullptr, DD, b2, 0);

    // 7) out = x + LN(f)
    ln_kernel<<<MROWS, 256>>>(x, t1, g2, be2, out, nullptr);
}

// round 12
// speedup vs baseline: 6.9149x; 1.0521x over previous
#include <cuda_runtime.h>
#include <cuda_fp16.h>
#include <stdint.h>

// Problem constants
#define BB 2
#define TT 2048
#define DD 1024
#define HH 16
#define DHH 64
#define FF 4096
#define MROWS (BB*TT)   // 4096

// ---------------------------------------------------------------------------
// Scratch (device globals; no allocations allowed)
// ---------------------------------------------------------------------------
__device__ __align__(16) __half g_packedWH[DD * 3 * DD]; // [1024 K][3072 N]
__device__ __align__(16) __half g_xh[MROWS * DD];        // half x
__device__ __align__(16) __half g_WoH[DD * DD];          // [1024][1024] natural
__device__ __align__(16) __half g_W1H[DD * FF];          // [1024][4096] natural
__device__ __align__(16) __half g_W2H[FF * DD];          // [4096][1024] natural
__device__ __align__(16) __half g_qkv[MROWS * 3 * DD];   // [4096][3072]
__device__ __align__(16) __half g_obuf[MROWS * DD];      // attention out
__device__ __align__(16) __half g_abuf[MROWS * DD];      // a (half)
__device__ __align__(16) __half g_h1[MROWS * FF];        // relu(a@W1+b1)
__device__ float g_t1[MROWS * DD];                       // f32 LN inputs

__device__ __forceinline__ void cp_async16(unsigned int s, const void* g) {
    asm volatile("cp.async.cg.shared.global [%0], [%1], 16;\n" :: "r"(s), "l"(g));
}

__device__ __forceinline__ void mma_f16(float* c, const unsigned int* a,
                                        unsigned int b0, unsigned int b1) {
    asm volatile(
        "mma.sync.aligned.m16n8k16.row.col.f32.f16.f16.f32 "
        "{%0,%1,%2,%3},{%4,%5,%6,%7},{%8,%9},{%0,%1,%2,%3};\n"
        : "+f"(c[0]), "+f"(c[1]), "+f"(c[2]), "+f"(c[3])
        : "r"(a[0]), "r"(a[1]), "r"(a[2]), "r"(a[3]), "r"(b0), "r"(b1));
}

__device__ __forceinline__ void ldsm4(unsigned int& r0, unsigned int& r1,
                                      unsigned int& r2, unsigned int& r3,
                                      unsigned int addr) {
    asm volatile("ldmatrix.sync.aligned.m8n8.x4.shared.b16 {%0,%1,%2,%3}, [%4];"
                 : "=r"(r0), "=r"(r1), "=r"(r2), "=r"(r3) : "r"(addr));
}

__device__ __forceinline__ void ldsm4t(unsigned int& r0, unsigned int& r1,
                                       unsigned int& r2, unsigned int& r3,
                                       unsigned int addr) {
    asm volatile("ldmatrix.sync.aligned.m8n8.x4.trans.shared.b16 {%0,%1,%2,%3}, [%4];"
                 : "=r"(r0), "=r"(r1), "=r"(r2), "=r"(r3) : "r"(addr));
}

// exp2 on the FMA pipe (x <= 0, clamped at -30). Max rel err ~4e-5.
__device__ __forceinline__ float fast_exp2(float x) {
    x = fmaxf(x, -30.f);
    float t = x + 12582912.f;
    int ni = __float_as_int(t) - 0x4B400000;
    float f = x - (t - 12582912.f);
    float p = 0.00961813f;
    p = fmaf(p, f, 0.0555041f);
    p = fmaf(p, f, 0.240227f);
    p = fmaf(p, f, 0.693147f);
    p = fmaf(p, f, 1.0f);
    return p * __int_as_float((ni + 127) << 23);
}

// ---------------------------------------------------------------------------
// f32 -> half streaming convert, 16 elems/thread (MLP 4)
// ---------------------------------------------------------------------------
__global__ __launch_bounds__(256) void tohalf16_kernel(
    const float* __restrict__ in, __half* __restrict__ out)
{
    long i = (long)(blockIdx.x * 256 + threadIdx.x) * 16;
    float4 v0 = *(const float4*)(in + i);
    float4 v1 = *(const float4*)(in + i + 4);
    float4 v2 = *(const float4*)(in + i + 8);
    float4 v3 = *(const float4*)(in + i + 12);
    __half2 h[8];
    h[0] = __floats2half2_rn(v0.x, v0.y); h[1] = __floats2half2_rn(v0.z, v0.w);
    h[2] = __floats2half2_rn(v1.x, v1.y); h[3] = __floats2half2_rn(v1.z, v1.w);
    h[4] = __floats2half2_rn(v2.x, v2.y); h[5] = __floats2half2_rn(v2.z, v2.w);
    h[6] = __floats2half2_rn(v3.x, v3.y); h[7] = __floats2half2_rn(v3.z, v3.w);
    *(uint4*)&out[i]     = *(uint4*)&h[0];
    *(uint4*)&out[i + 8] = *(uint4*)&h[4];
}

// ---------------------------------------------------------------------------
// QKV regroup + convert (coalesced both sides, no transpose):
// dst[d][w*1024 + h*64 + e] = half(W_w[h][d][e]).
// grid (32, 48): blockIdx.x = d/32, blockIdx.y = w*16+h. 256 thr = 32 d x 8 e8.
// ---------------------------------------------------------------------------
__global__ __launch_bounds__(256) void convert_qkv_kernel(
    const float* __restrict__ Wq, const float* __restrict__ Wk,
    const float* __restrict__ Wv, __half* __restrict__ dst)
{
    int w = blockIdx.y >> 4, h = blockIdx.y & 15;
    int d = blockIdx.x * 32 + (threadIdx.x >> 3);
    int e = (threadIdx.x & 7) * 8;
    const float* src = ((w == 0) ? Wq : (w == 1) ? Wk : Wv)
                       + (long)h * (DD * DHH) + (long)d * DHH + e;
    float4 v0 = *(const float4*)src;
    float4 v1 = *(const float4*)(src + 4);
    __half2 hh[4];
    hh[0] = __floats2half2_rn(v0.x, v0.y); hh[1] = __floats2half2_rn(v0.z, v0.w);
    hh[2] = __floats2half2_rn(v1.x, v1.y); hh[3] = __floats2half2_rn(v1.z, v1.w);
    *(uint4*)&dst[(long)d * 3072 + w * 1024 + h * 64 + e] = *(uint4*)hh;
}

// ---------------------------------------------------------------------------
// fp16 tensor-core GEMM, natural-layout B via ldmatrix.trans.
// C = A[M,K] * B[K,N] (+bias)(+relu); 128x128 tile, K-chunk 64, 2-stage.
// A row-major half [M][K]; B row-major half [K][N].
// ---------------------------------------------------------------------------
#define ASTR 72                            // A smem stride (halves)
#define BSTR 136                           // B smem stride (halves)
#define A_ST_B (128 * ASTR * 2)            // 18432
#define B_ST_B (64 * BSTR * 2)             // 17408
#define HSTAGE_B (A_ST_B + B_ST_B)         // 35840
#define HGEMM_SMEM (2 * HSTAGE_B)          // 71680

__global__ __launch_bounds__(256, 2) void hgemm_kernel(
    const __half* __restrict__ A, int lda,
    const __half* __restrict__ B, int ldb, int K,
    float* __restrict__ Cf, __half* __restrict__ Ch, int ldc,
    const float* __restrict__ bias, int do_relu)
{
    extern __shared__ __align__(16) char dsm[];
    const int tid  = threadIdx.x;
    const int lane = tid & 31;
    const int warp = tid >> 5;
    const int gid  = lane >> 2;
    const int tig  = lane & 3;
    const int wm   = warp & 1;
    const int wn   = warp >> 1;
    const int rowBase = blockIdx.y * 128;
    const int colBase = blockIdx.x * 128;
    const unsigned int smem_u = (unsigned int)__cvta_generic_to_shared(dsm);

    // ldmatrix per-lane byte offsets within stage
    const unsigned int aOff = ((wm * 64 + (lane & 15)) * ASTR + ((lane & 16) >> 1)) * 2;
    const unsigned int bOff = A_ST_B +
        ((lane & 15) * BSTR + wn * 32 + ((lane & 16) >> 1)) * 2;

    float acc[16][4];
    #pragma unroll
    for (int i = 0; i < 16; i++)
        #pragma unroll
        for (int j = 0; j < 4; j++) acc[i][j] = 0.f;

    auto issue = [&](int stage, int k0) {
        unsigned int st = smem_u + stage * HSTAGE_B;
        #pragma unroll
        for (int p = 0; p < 4; p++) {            // A: 128 rows x 8 x 16B
            int i = tid + p * 256;
            int r = i >> 3, q = i & 7;
            cp_async16(st + r * (ASTR * 2) + q * 16,
                       A + (long)(rowBase + r) * lda + k0 + q * 8);
        }
        #pragma unroll
        for (int p = 0; p < 4; p++) {            // B: 64 k-rows x 16 x 16B
            int i = tid + p * 256;
            int r = i >> 4, q = i & 15;
            cp_async16(st + A_ST_B + r * (BSTR * 2) + q * 16,
                       B + (long)(k0 + r) * ldb + colBase + q * 8);
        }
        asm volatile("cp.async.commit_group;\n");
    };

    issue(0, 0);
    const int nk = K / 64;

    for (int kt = 0; kt < nk; kt++) {
        if (kt + 1 < nk) {
            issue((kt + 1) & 1, (kt + 1) * 64);
            asm volatile("cp.async.wait_group 1;\n");
        } else {
            asm volatile("cp.async.wait_group 0;\n");
        }
        __syncthreads();

        const unsigned int st = smem_u + (kt & 1) * HSTAGE_B;

        #pragma unroll
        for (int ks = 0; ks < 4; ks++) {
            unsigned int a[4][4], b[2][4];
            #pragma unroll
            for (int mt = 0; mt < 4; mt++)
                ldsm4(a[mt][0], a[mt][1], a[mt][2], a[mt][3],
                      st + aOff + mt * 16 * ASTR * 2 + ks * 32);
            #pragma unroll
            for (int pr = 0; pr < 2; pr++)       // B trans: 16k x 16n block
                ldsm4t(b[pr][0], b[pr][1], b[pr][2], b[pr][3],
                       st + bOff + ks * 16 * BSTR * 2 + pr * 32);
            #pragma unroll
            for (int mt = 0; mt < 4; mt++) {
                mma_f16(acc[mt * 4 + 0], a[mt], b[0][0], b[0][1]);
                mma_f16(acc[mt * 4 + 1], a[mt], b[0][2], b[0][3]);
                mma_f16(acc[mt * 4 + 2], a[mt], b[1][0], b[1][1]);
                mma_f16(acc[mt * 4 + 3], a[mt], b[1][2], b[1][3]);
            }
        }
        __syncthreads();
    }

    // epilogue
    #pragma unroll
    for (int mt = 0; mt < 4; mt++) {
        int r0 = rowBase + wm * 64 + mt * 16 + gid;
        #pragma unroll
        for (int nt = 0; nt < 4; nt++) {
            int c = colBase + wn * 32 + nt * 8 + tig * 2;
            float* v = acc[mt * 4 + nt];
            float o0 = v[0], o1 = v[1], o2 = v[2], o3 = v[3];
            if (bias) {
                float b0 = bias[c], b1 = bias[c + 1];
                o0 += b0; o1 += b1; o2 += b0; o3 += b1;
            }
            if (do_relu) {
                o0 = fmaxf(o0, 0.f); o1 = fmaxf(o1, 0.f);
                o2 = fmaxf(o2, 0.f); o3 = fmaxf(o3, 0.f);
            }
            if (Ch) {
                *(__half2*)&Ch[(long)r0 * ldc + c]       = __floats2half2_rn(o0, o1);
                *(__half2*)&Ch[(long)(r0 + 8) * ldc + c] = __floats2half2_rn(o2, o3);
            } else {
                *(float2*)&Cf[(long)r0 * ldc + c]       = make_float2(o0, o1);
                *(float2*)&Cf[(long)(r0 + 8) * ldc + c] = make_float2(o2, o3);
            }
        }
    }
}

// ---------------------------------------------------------------------------
// fp16 causal flash attention: cp.async K/V double-buffer, natural V with
// ldmatrix.trans fragments (no scalar transpose), FMA-pipe exp2.
// 256 threads (8 warps), Q tile 128 rows, warp owns 16 rows, K tile 64.
// ---------------------------------------------------------------------------
#define AQ 72
// halves: Qs 128 rows, K ring 2x64, V ring 2x64, Ps 128
#define ATTN_SMEM_BYTES ((128 + 128 + 128 + 128) * AQ * 2)   // 73728

__global__ __launch_bounds__(256) void attn_h_kernel(
    const __half* __restrict__ qkv, __half* __restrict__ obuf)
{
    extern __shared__ __align__(16) __half hsm[];
    __half* Qs = hsm;                    // [128][AQ]
    __half* Kr = Qs + 128 * AQ;          // 2 x [64][AQ]  K natural [tok][dim]
    __half* Vr = Kr + 128 * AQ;          // 2 x [64][AQ]  V natural [tok][dim]
    __half* Ps = Vr + 128 * AQ;          // [128][AQ]

    const int tid  = threadIdx.x;
    const int lane = tid & 31;
    const int warp = tid >> 5;
    const int gid  = lane >> 2;
    const int tig  = lane & 3;
    const int iq   = (int)gridDim.x - 1 - (int)blockIdx.x;
    const int h    = blockIdx.y;
    const int b    = blockIdx.z;
    const int rowbase = iq * 128;
    const int mrow = warp * 16;
    const long base = (long)b * TT * 3072;

    const unsigned int qs_u = (unsigned int)__cvta_generic_to_shared(Qs);
    const unsigned int kr_u = (unsigned int)__cvta_generic_to_shared(Kr);
    const unsigned int vr_u = (unsigned int)__cvta_generic_to_shared(Vr);
    const unsigned int ps_u = (unsigned int)__cvta_generic_to_shared(Ps);

    // ldmatrix per-lane byte offsets
    const unsigned int aOffQ = ((mrow + (lane & 15)) * AQ + ((lane & 16) >> 1)) * 2;
    const unsigned int bRowK = (lane & 7) + ((lane >> 1) & 8);
    const unsigned int bOffK = (bRowK * AQ + (lane & 8)) * 2;
    const unsigned int vOffB = ((lane & 15) * AQ + ((lane & 16) >> 1)) * 2;

    // Load Q tile [128][64]
    {
        int r  = tid >> 1;
        int dg = (tid & 1) * 32;
        const __half* qp = qkv + base + (long)(rowbase + r) * 3072 + h * 64 + dg;
        #pragma unroll
        for (int it = 0; it < 4; it++)
            *(uint4*)&Qs[r * AQ + dg + it * 8] = *(const uint4*)(qp + it * 8);
    }

    auto issue_kv = [&](int jt, int s) {
        unsigned int kst = kr_u + s * (64 * AQ * 2);
        unsigned int vst = vr_u + s * (64 * AQ * 2);
        #pragma unroll
        for (int p = 0; p < 2; p++) {            // K: 64 rows x 8 x 16B
            int i = tid + p * 256;
            int r = i >> 3, q = i & 7;
            const __half* kp = qkv + base + (long)(jt * 64 + r) * 3072 + 1024 + h * 64 + q * 8;
            cp_async16(kst + r * (AQ * 2) + q * 16, kp);
        }
        #pragma unroll
        for (int p = 0; p < 2; p++) {            // V: 64 rows x 8 x 16B
            int i = tid + p * 256;
            int r = i >> 3, q = i & 7;
            const __half* vp = qkv + base + (long)(jt * 64 + r) * 3072 + 2048 + h * 64 + q * 8;
            cp_async16(vst + r * (AQ * 2) + q * 16, vp);
        }
        asm volatile("cp.async.commit_group;\n");
    };

    const float sscale = 0.125f * 1.44269504f;
    float m0 = -1e30f, m1 = -1e30f, l0 = 0.f, l1 = 0.f;
    float o_[8][4];
    #pragma unroll
    for (int nt = 0; nt < 8; nt++)
        #pragma unroll
        for (int j = 0; j < 4; j++) o_[nt][j] = 0.f;

    const int row0 = rowbase + mrow + gid;
    const int row1 = row0 + 8;
    const int jmax = (rowbase >> 6) + 1;

    issue_kv(0, 0);

    for (int jt = 0; jt <= jmax; jt++) {
        asm volatile("cp.async.wait_group 0;\n");
        __syncthreads();
        if (jt < jmax) issue_kv(jt + 1, (jt + 1) & 1);

        if (jt * 64 > rowbase + mrow + 15) continue;

        const unsigned int kst = kr_u + (jt & 1) * (64 * AQ * 2);
        const unsigned int vst = vr_u + (jt & 1) * (64 * AQ * 2);

        // S = Q K^T
        float s[8][4];
        #pragma unroll
        for (int nt = 0; nt < 8; nt++)
            #pragma unroll
            for (int j = 0; j < 4; j++) s[nt][j] = 0.f;

        #pragma unroll
        for (int kk = 0; kk < 64; kk += 16) {
            unsigned int a[4], bk[4][4];
            ldsm4(a[0], a[1], a[2], a[3], qs_u + aOffQ + kk * 2);
            #pragma unroll
            for (int pr = 0; pr < 4; pr++)
                ldsm4(bk[pr][0], bk[pr][1], bk[pr][2], bk[pr][3],
                      kst + bOffK + pr * 16 * AQ * 2 + kk * 2);
            #pragma unroll
            for (int pr = 0; pr < 4; pr++) {
                mma_f16(s[pr * 2 + 0], a, bk[pr][0], bk[pr][1]);
                mma_f16(s[pr * 2 + 1], a, bk[pr][2], bk[pr][3]);
            }
        }

        const bool need_mask = (jt * 64 + 63 > rowbase + mrow);
        #pragma unroll
        for (int nt = 0; nt < 8; nt++) {
            int col = jt * 64 + nt * 8 + tig * 2;
            if (need_mask) {
                s[nt][0] = (col     <= row0) ? s[nt][0] * sscale : -1e30f;
                s[nt][1] = (col + 1 <= row0) ? s[nt][1] * sscale : -1e30f;
                s[nt][2] = (col     <= row1) ? s[nt][2] * sscale : -1e30f;
                s[nt][3] = (col + 1 <= row1) ? s[nt][3] * sscale : -1e30f;
            } else {
                s[nt][0] *= sscale; s[nt][1] *= sscale;
                s[nt][2] *= sscale; s[nt][3] *= sscale;
            }
        }

        float tm0 = -1e30f, tm1 = -1e30f;
        #pragma unroll
        for (int nt = 0; nt < 8; nt++) {
            tm0 = fmaxf(tm0, fmaxf(s[nt][0], s[nt][1]));
            tm1 = fmaxf(tm1, fmaxf(s[nt][2], s[nt][3]));
        }
        tm0 = fmaxf(tm0, __shfl_xor_sync(0xffffffffu, tm0, 1));
        tm0 = fmaxf(tm0, __shfl_xor_sync(0xffffffffu, tm0, 2));
        tm1 = fmaxf(tm1, __shfl_xor_sync(0xffffffffu, tm1, 1));
        tm1 = fmaxf(tm1, __shfl_xor_sync(0xffffffffu, tm1, 2));

        float mn0 = fmaxf(m0, tm0);
        float mn1 = fmaxf(m1, tm1);
        float corr0 = fast_exp2(m0 - mn0);
        float corr1 = fast_exp2(m1 - mn1);

        float rs0 = 0.f, rs1 = 0.f;
        #pragma unroll
        for (int nt = 0; nt < 8; nt++) {
            float p00 = fast_exp2(s[nt][0] - mn0);
            float p01 = fast_exp2(s[nt][1] - mn0);
            float p10 = fast_exp2(s[nt][2] - mn1);
            float p11 = fast_exp2(s[nt][3] - mn1);
            rs0 += p00 + p01;
            rs1 += p10 + p11;
            *(__half2*)&Ps[(mrow + gid    ) * AQ + nt * 8 + tig * 2] = __floats2half2_rn(p00, p01);
            *(__half2*)&Ps[(mrow + gid + 8) * AQ + nt * 8 + tig * 2] = __floats2half2_rn(p10, p11);
        }
        rs0 += __shfl_xor_sync(0xffffffffu, rs0, 1);
        rs0 += __shfl_xor_sync(0xffffffffu, rs0, 2);
        rs1 += __shfl_xor_sync(0xffffffffu, rs1, 1);
        rs1 += __shfl_xor_sync(0xffffffffu, rs1, 2);

        l0 = l0 * corr0 + rs0;  m0 = mn0;
        l1 = l1 * corr1 + rs1;  m1 = mn1;
        #pragma unroll
        for (int nt = 0; nt < 8; nt++) {
            o_[nt][0] *= corr0; o_[nt][1] *= corr0;
            o_[nt][2] *= corr1; o_[nt][3] *= corr1;
        }
        __syncwarp();

        // O += P V   (A = Ps rows [m][tok]; B = V natural [tok][dim] via trans)
        #pragma unroll
        for (int kk = 0; kk < 64; kk += 16) {
            unsigned int a[4], bv[4][4];
            ldsm4(a[0], a[1], a[2], a[3], ps_u + aOffQ + kk * 2);
            #pragma unroll
            for (int pr = 0; pr < 4; pr++)
                ldsm4t(bv[pr][0], bv[pr][1], bv[pr][2], bv[pr][3],
                       vst + vOffB + kk * AQ * 2 + pr * 32);
            #pragma unroll
            for (int pr = 0; pr < 4; pr++) {
                mma_f16(o_[pr * 2 + 0], a, bv[pr][0], bv[pr][1]);
                mma_f16(o_[pr * 2 + 1], a, bv[pr][2], bv[pr][3]);
            }
        }
    }

    float inv0 = 1.f / l0;
    float inv1 = 1.f / l1;
    #pragma unroll
    for (int nt = 0; nt < 8; nt++) {
        int c = h * 64 + nt * 8 + tig * 2;
        *(__half2*)&obuf[(long)(b * TT + row0) * DD + c] =
            __floats2half2_rn(o_[nt][0] * inv0, o_[nt][1] * inv0);
        *(__half2*)&obuf[(long)(b * TT + row1) * DD + c] =
            __floats2half2_rn(o_[nt][2] * inv1, o_[nt][3] * inv1);
    }
}

// ---------------------------------------------------------------------------
// out = x + LayerNorm(y)*g + be ; writes f32 (outf) or half (outh).
// ---------------------------------------------------------------------------
__global__ __launch_bounds__(256) void ln_kernel(
    const float* __restrict__ x, const float* __restrict__ y,
    const float* __restrict__ g, const float* __restrict__ be,
    float* __restrict__ outf, __half* __restrict__ outh)
{
    int row = blockIdx.x;
    int tid = threadIdx.x;
    float4 v = ((const float4*)(y + (long)row * DD))[tid];
    float s  = v.x + v.y + v.z + v.w;
    float ss = v.x * v.x + v.y * v.y + v.z * v.z + v.w * v.w;
    #pragma unroll
    for (int off = 16; off >= 1; off >>= 1) {
        s  += __shfl_xor_sync(0xffffffffu, s,  off);
        ss += __shfl_xor_sync(0xffffffffu, ss, off);
    }
    __shared__ float sb[8], ssb[8];
    if ((tid & 31) == 0) { sb[tid >> 5] = s; ssb[tid >> 5] = ss; }
    __syncthreads();
    float tot = 0.f, tots = 0.f;
    #pragma unroll
    for (int w = 0; w < 8; w++) { tot += sb[w]; tots += ssb[w]; }
    float mu = tot * (1.f / 1024.f);
    float var = tots * (1.f / 1024.f) - mu * mu;
    float rstd = rsqrtf(var + 1e-5f);

    float4 xv = ((const float4*)(x + (long)row * DD))[tid];
    float4 gv = ((const float4*)g)[tid];
    float4 bv = ((const float4*)be)[tid];
    float4 o;
    o.x = xv.x + (v.x - mu) * rstd * gv.x + bv.x;
    o.y = xv.y + (v.y - mu) * rstd * gv.y + bv.y;
    o.z = xv.z + (v.z - mu) * rstd * gv.z + bv.z;
    o.w = xv.w + (v.w - mu) * rstd * gv.w + bv.w;
    if (outh) {
        __half2 h0 = __floats2half2_rn(o.x, o.y);
        __half2 h1 = __floats2half2_rn(o.z, o.w);
        *(__half2*)&outh[(long)row * DD + tid * 4]     = h0;
        *(__half2*)&outh[(long)row * DD + tid * 4 + 2] = h1;
    } else {
        ((float4*)(outf + (long)row * DD))[tid] = o;
    }
}

// ---------------------------------------------------------------------------
// launch
// ---------------------------------------------------------------------------
extern "C" void kernel_launch(void* const* d_in, const int* in_sizes, int n_in,
                              void* d_out, int out_size)
{
    const float* x   = (const float*)d_in[0];
    const float* Wq  = (const float*)d_in[1];
    const float* Wk  = (const float*)d_in[2];
    const float* Wv  = (const float*)d_in[3];
    const float* Wo  = (const float*)d_in[4];
    const float* bo  = (const float*)d_in[5];
    const float* W1  = (const float*)d_in[6];
    const float* b1  = (const float*)d_in[7];
    const float* W2  = (const float*)d_in[8];
    const float* b2  = (const float*)d_in[9];
    const float* g1  = (const float*)d_in[10];
    const float* be1 = (const float*)d_in[11];
    const float* g2  = (const float*)d_in[12];
    const float* be2 = (const float*)d_in[13];
    float* out = (float*)d_out;

    __half *packedWH, *xh, *WoH, *W1H, *W2H, *qkv, *obuf, *abuf, *h1;
    float *t1;
    cudaGetSymbolAddress((void**)&packedWH, g_packedWH);
    cudaGetSymbolAddress((void**)&xh,       g_xh);
    cudaGetSymbolAddress((void**)&WoH,      g_WoH);
    cudaGetSymbolAddress((void**)&W1H,      g_W1H);
    cudaGetSymbolAddress((void**)&W2H,      g_W2H);
    cudaGetSymbolAddress((void**)&qkv,      g_qkv);
    cudaGetSymbolAddress((void**)&obuf,     g_obuf);
    cudaGetSymbolAddress((void**)&abuf,     g_abuf);
    cudaGetSymbolAddress((void**)&h1,       g_h1);
    cudaGetSymbolAddress((void**)&t1,       g_t1);

    cudaFuncSetAttribute(attn_h_kernel,
                         cudaFuncAttributeMaxDynamicSharedMemorySize, ATTN_SMEM_BYTES);
    cudaFuncSetAttribute(hgemm_kernel,
                         cudaFuncAttributeMaxDynamicSharedMemorySize, HGEMM_SMEM);

    // 0) prep: streaming converts (natural layouts) + QKV regroup
    tohalf16_kernel<<<(MROWS * DD) / 4096, 256>>>(x,  xh);
    tohalf16_kernel<<<(DD * DD)    / 4096, 256>>>(Wo, WoH);
    tohalf16_kernel<<<(DD * FF)    / 4096, 256>>>(W1, W1H);
    tohalf16_kernel<<<(FF * DD)    / 4096, 256>>>(W2, W2H);
    convert_qkv_kernel<<<dim3(32, 48), 256>>>(Wq, Wk, Wv, packedWH);

    // 1) qkv = xh @ packedW -> half
    hgemm_kernel<<<dim3(3 * DD / 128, MROWS / 128), 256, HGEMM_SMEM>>>(
        xh, DD, packedWH, 3 * DD, DD, nullptr, qkv, 3 * DD, nullptr, 0);

    // 2) attention -> half obuf
    attn_h_kernel<<<dim3(TT / 128, HH, BB), 256, ATTN_SMEM_BYTES>>>(qkv, obuf);

    // 3) attn_out = obuf @ Wo + bo -> f32 t1
    hgemm_kernel<<<dim3(DD / 128, MROWS / 128), 256, HGEMM_SMEM>>>(
        obuf, DD, WoH, DD, DD, t1, nullptr, DD, bo, 0);

    // 4) a = x + LN(attn_out) -> half abuf
    ln_kernel<<<MROWS, 256>>>(x, t1, g1, be1, nullptr, abuf);

    // 5) h1 = relu(a @ W1 + b1) -> half
    hgemm_kernel<<<dim3(FF / 128, MROWS / 128), 256, HGEMM_SMEM>>>(
        abuf, DD, W1H, FF, DD, nullptr, h1, FF, b1, 1);

    // 6) f = h1 @ W2 + b2 -> f32 t1
    hgemm_kernel<<<dim3(DD / 128, MROWS / 128), 256, HGEMM_SMEM>>>(
        h1, FF, W2H, DD, FF, t1, nullptr, DD, b2, 0);

    // 7) out = x + LN(f)
    ln_kernel<<<MROWS, 256>>>(x, t1, g2, be2, out, nullptr);
}

// round 13
// speedup vs baseline: 7.2023x; 1.0416x over previous
#include <cuda_runtime.h>
#include <cuda_fp16.h>
#include <stdint.h>

// Problem constants
#define BB 2
#define TT 2048
#define DD 1024
#define HH 16
#define DHH 64
#define FF 4096
#define MROWS (BB*TT)   // 4096

// ---------------------------------------------------------------------------
// Scratch (device globals; no allocations allowed)
// ---------------------------------------------------------------------------
__device__ __align__(16) __half g_packedWH[DD * 3 * DD]; // [1024 K][3072 N]
__device__ __align__(16) __half g_xh[MROWS * DD];        // half x
__device__ __align__(16) __half g_WoH[DD * DD];          // [1024][1024] natural
__device__ __align__(16) __half g_W1H[DD * FF];          // [1024][4096] natural
__device__ __align__(16) __half g_W2H[FF * DD];          // [4096][1024] natural
__device__ __align__(16) __half g_qkv[MROWS * 3 * DD];   // [4096][3072]
__device__ __align__(16) __half g_obuf[MROWS * DD];      // attention out
__device__ __align__(16) __half g_abuf[MROWS * DD];      // a (half)
__device__ __align__(16) __half g_h1[MROWS * FF];        // relu(a@W1+b1)
__device__ float g_t1[MROWS * DD];                       // f32 LN inputs

__device__ __forceinline__ void cp_async16(unsigned int s, const void* g) {
    asm volatile("cp.async.cg.shared.global [%0], [%1], 16;\n" :: "r"(s), "l"(g));
}

__device__ __forceinline__ void mma_f16(float* c, const unsigned int* a,
                                        unsigned int b0, unsigned int b1) {
    asm volatile(
        "mma.sync.aligned.m16n8k16.row.col.f32.f16.f16.f32 "
        "{%0,%1,%2,%3},{%4,%5,%6,%7},{%8,%9},{%0,%1,%2,%3};\n"
        : "+f"(c[0]), "+f"(c[1]), "+f"(c[2]), "+f"(c[3])
        : "r"(a[0]), "r"(a[1]), "r"(a[2]), "r"(a[3]), "r"(b0), "r"(b1));
}

__device__ __forceinline__ void ldsm4(unsigned int& r0, unsigned int& r1,
                                      unsigned int& r2, unsigned int& r3,
                                      unsigned int addr) {
    asm volatile("ldmatrix.sync.aligned.m8n8.x4.shared.b16 {%0,%1,%2,%3}, [%4];"
                 : "=r"(r0), "=r"(r1), "=r"(r2), "=r"(r3) : "r"(addr));
}

__device__ __forceinline__ void ldsm4t(unsigned int& r0, unsigned int& r1,
                                       unsigned int& r2, unsigned int& r3,
                                       unsigned int addr) {
    asm volatile("ldmatrix.sync.aligned.m8n8.x4.trans.shared.b16 {%0,%1,%2,%3}, [%4];"
                 : "=r"(r0), "=r"(r1), "=r"(r2), "=r"(r3) : "r"(addr));
}

// exp2 on the FMA pipe (x <= 0, clamped at -30). Max rel err ~4e-5.
__device__ __forceinline__ float fast_exp2(float x) {
    x = fmaxf(x, -30.f);
    float t = x + 12582912.f;
    int ni = __float_as_int(t) - 0x4B400000;
    float f = x - (t - 12582912.f);
    float p = 0.00961813f;
    p = fmaf(p, f, 0.0555041f);
    p = fmaf(p, f, 0.240227f);
    p = fmaf(p, f, 0.693147f);
    p = fmaf(p, f, 1.0f);
    return p * __int_as_float((ni + 127) << 23);
}

// ---------------------------------------------------------------------------
// Fused f32 -> f16 convert for x, Wo, W1, W2 (one launch).
// Segments (elements): x 4M | Wo 1M | W1 4M | W2 4M. 16 elems/thread.
// ---------------------------------------------------------------------------
#define SEG0 (MROWS * DD)            // 4194304
#define SEG1 (SEG0 + DD * DD)        // 5242880
#define SEG2 (SEG1 + DD * FF)        // 9437184
#define SEG3 (SEG2 + FF * DD)        // 13631488

__global__ __launch_bounds__(256) void convert_all_kernel(
    const float* __restrict__ x,  const float* __restrict__ Wo,
    const float* __restrict__ W1, const float* __restrict__ W2,
    __half* __restrict__ xh,  __half* __restrict__ WoH,
    __half* __restrict__ W1H, __half* __restrict__ W2H)
{
    long i = (long)(blockIdx.x * 256 + threadIdx.x) * 16;
    const float* src; __half* dst; long off;
    if (i < SEG0)      { src = x;  dst = xh;  off = i; }
    else if (i < SEG1) { src = Wo; dst = WoH; off = i - SEG0; }
    else if (i < SEG2) { src = W1; dst = W1H; off = i - SEG1; }
    else               { src = W2; dst = W2H; off = i - SEG2; }
    float4 v0 = *(const float4*)(src + off);
    float4 v1 = *(const float4*)(src + off + 4);
    float4 v2 = *(const float4*)(src + off + 8);
    float4 v3 = *(const float4*)(src + off + 12);
    __half2 h[8];
    h[0] = __floats2half2_rn(v0.x, v0.y); h[1] = __floats2half2_rn(v0.z, v0.w);
    h[2] = __floats2half2_rn(v1.x, v1.y); h[3] = __floats2half2_rn(v1.z, v1.w);
    h[4] = __floats2half2_rn(v2.x, v2.y); h[5] = __floats2half2_rn(v2.z, v2.w);
    h[6] = __floats2half2_rn(v3.x, v3.y); h[7] = __floats2half2_rn(v3.z, v3.w);
    *(uint4*)&dst[off]     = *(uint4*)&h[0];
    *(uint4*)&dst[off + 8] = *(uint4*)&h[4];
}

// ---------------------------------------------------------------------------
// QKV regroup + convert: dst[d][w*1024 + h*64 + e] = half(W_w[h][d][e]).
// ---------------------------------------------------------------------------
__global__ __launch_bounds__(256) void convert_qkv_kernel(
    const float* __restrict__ Wq, const float* __restrict__ Wk,
    const float* __restrict__ Wv, __half* __restrict__ dst)
{
    int w = blockIdx.y >> 4, h = blockIdx.y & 15;
    int d = blockIdx.x * 32 + (threadIdx.x >> 3);
    int e = (threadIdx.x & 7) * 8;
    const float* src = ((w == 0) ? Wq : (w == 1) ? Wk : Wv)
                       + (long)h * (DD * DHH) + (long)d * DHH + e;
    float4 v0 = *(const float4*)src;
    float4 v1 = *(const float4*)(src + 4);
    __half2 hh[4];
    hh[0] = __floats2half2_rn(v0.x, v0.y); hh[1] = __floats2half2_rn(v0.z, v0.w);
    hh[2] = __floats2half2_rn(v1.x, v1.y); hh[3] = __floats2half2_rn(v1.z, v1.w);
    *(uint4*)&dst[(long)d * 3072 + w * 1024 + h * 64 + e] = *(uint4*)hh;
}

// ---------------------------------------------------------------------------
// fp16 tensor-core GEMM, natural-layout B via ldmatrix.trans (proven R12 core)
// ---------------------------------------------------------------------------
#define ASTR 72
#define BSTR 136
#define A_ST_B (128 * ASTR * 2)            // 18432
#define B_ST_B (64 * BSTR * 2)             // 17408
#define HSTAGE_B (A_ST_B + B_ST_B)         // 35840
#define HGEMM_SMEM (2 * HSTAGE_B)          // 71680

__global__ __launch_bounds__(256, 2) void hgemm_kernel(
    const __half* __restrict__ A, int lda,
    const __half* __restrict__ B, int ldb, int K,
    float* __restrict__ Cf, __half* __restrict__ Ch, int ldc,
    const float* __restrict__ bias, int do_relu)
{
    extern __shared__ __align__(16) char dsm[];
    const int tid  = threadIdx.x;
    const int lane = tid & 31;
    const int warp = tid >> 5;
    const int gid  = lane >> 2;
    const int tig  = lane & 3;
    const int wm   = warp & 1;
    const int wn   = warp >> 1;
    const int rowBase = blockIdx.y * 128;
    const int colBase = blockIdx.x * 128;
    const unsigned int smem_u = (unsigned int)__cvta_generic_to_shared(dsm);

    const unsigned int aOff = ((wm * 64 + (lane & 15)) * ASTR + ((lane & 16) >> 1)) * 2;
    const unsigned int bOff = A_ST_B +
        ((lane & 15) * BSTR + wn * 32 + ((lane & 16) >> 1)) * 2;

    float acc[16][4];
    #pragma unroll
    for (int i = 0; i < 16; i++)
        #pragma unroll
        for (int j = 0; j < 4; j++) acc[i][j] = 0.f;

    auto issue = [&](int stage, int k0) {
        unsigned int st = smem_u + stage * HSTAGE_B;
        #pragma unroll
        for (int p = 0; p < 4; p++) {
            int i = tid + p * 256;
            int r = i >> 3, q = i & 7;
            cp_async16(st + r * (ASTR * 2) + q * 16,
                       A + (long)(rowBase + r) * lda + k0 + q * 8);
        }
        #pragma unroll
        for (int p = 0; p < 4; p++) {
            int i = tid + p * 256;
            int r = i >> 4, q = i & 15;
            cp_async16(st + A_ST_B + r * (BSTR * 2) + q * 16,
                       B + (long)(k0 + r) * ldb + colBase + q * 8);
        }
        asm volatile("cp.async.commit_group;\n");
    };

    issue(0, 0);
    const int nk = K / 64;

    for (int kt = 0; kt < nk; kt++) {
        if (kt + 1 < nk) {
            issue((kt + 1) & 1, (kt + 1) * 64);
            asm volatile("cp.async.wait_group 1;\n");
        } else {
            asm volatile("cp.async.wait_group 0;\n");
        }
        __syncthreads();

        const unsigned int st = smem_u + (kt & 1) * HSTAGE_B;

        #pragma unroll
        for (int ks = 0; ks < 4; ks++) {
            unsigned int a[4][4], b[2][4];
            #pragma unroll
            for (int mt = 0; mt < 4; mt++)
                ldsm4(a[mt][0], a[mt][1], a[mt][2], a[mt][3],
                      st + aOff + mt * 16 * ASTR * 2 + ks * 32);
            #pragma unroll
            for (int pr = 0; pr < 2; pr++)
                ldsm4t(b[pr][0], b[pr][1], b[pr][2], b[pr][3],
                       st + bOff + ks * 16 * BSTR * 2 + pr * 32);
            #pragma unroll
            for (int mt = 0; mt < 4; mt++) {
                mma_f16(acc[mt * 4 + 0], a[mt], b[0][0], b[0][1]);
                mma_f16(acc[mt * 4 + 1], a[mt], b[0][2], b[0][3]);
                mma_f16(acc[mt * 4 + 2], a[mt], b[1][0], b[1][1]);
                mma_f16(acc[mt * 4 + 3], a[mt], b[1][2], b[1][3]);
            }
        }
        __syncthreads();
    }

    #pragma unroll
    for (int mt = 0; mt < 4; mt++) {
        int r0 = rowBase + wm * 64 + mt * 16 + gid;
        #pragma unroll
        for (int nt = 0; nt < 4; nt++) {
            int c = colBase + wn * 32 + nt * 8 + tig * 2;
            float* v = acc[mt * 4 + nt];
            float o0 = v[0], o1 = v[1], o2 = v[2], o3 = v[3];
            if (bias) {
                float b0 = bias[c], b1 = bias[c + 1];
                o0 += b0; o1 += b1; o2 += b0; o3 += b1;
            }
            if (do_relu) {
                o0 = fmaxf(o0, 0.f); o1 = fmaxf(o1, 0.f);
                o2 = fmaxf(o2, 0.f); o3 = fmaxf(o3, 0.f);
            }
            if (Ch) {
                *(__half2*)&Ch[(long)r0 * ldc + c]       = __floats2half2_rn(o0, o1);
                *(__half2*)&Ch[(long)(r0 + 8) * ldc + c] = __floats2half2_rn(o2, o3);
            } else {
                *(float2*)&Cf[(long)r0 * ldc + c]       = make_float2(o0, o1);
                *(float2*)&Cf[(long)(r0 + 8) * ldc + c] = make_float2(o2, o3);
            }
        }
    }
}

// ---------------------------------------------------------------------------
// fp16 causal flash attention: Q fragments in registers, cp.async KV ring,
// natural V via ldmatrix.trans, FMA-pipe exp2. smem 55296 B -> 4 blocks/SM.
// ---------------------------------------------------------------------------
#define AQ 72
// halves: K ring 2x64 rows, V ring 2x64 rows, Ps 128 rows (Q staged in Ps)
#define ATTN_SMEM_BYTES ((128 + 128 + 128) * AQ * 2)   // 55296

__global__ __launch_bounds__(256) void attn_h_kernel(
    const __half* __restrict__ qkv, __half* __restrict__ obuf)
{
    extern __shared__ __align__(16) __half hsm[];
    __half* Kr = hsm;                    // 2 x [64][AQ]
    __half* Vr = Kr + 128 * AQ;          // 2 x [64][AQ]
    __half* Ps = Vr + 128 * AQ;          // [128][AQ]  (Q staging, then P)

    const int tid  = threadIdx.x;
    const int lane = tid & 31;
    const int warp = tid >> 5;
    const int gid  = lane >> 2;
    const int tig  = lane & 3;
    const int iq   = (int)gridDim.x - 1 - (int)blockIdx.x;
    const int h    = blockIdx.y;
    const int b    = blockIdx.z;
    const int rowbase = iq * 128;
    const int mrow = warp * 16;
    const long base = (long)b * TT * 3072;

    const unsigned int kr_u = (unsigned int)__cvta_generic_to_shared(Kr);
    const unsigned int vr_u = (unsigned int)__cvta_generic_to_shared(Vr);
    const unsigned int ps_u = (unsigned int)__cvta_generic_to_shared(Ps);

    const unsigned int aOffP = ((mrow + (lane & 15)) * AQ + ((lane & 16) >> 1)) * 2;
    const unsigned int bRowK = (lane & 7) + ((lane >> 1) & 8);
    const unsigned int bOffK = (bRowK * AQ + (lane & 8)) * 2;
    const unsigned int vOffB = ((lane & 15) * AQ + ((lane & 16) >> 1)) * 2;

    auto issue_kv = [&](int jt, int s) {
        unsigned int kst = kr_u + s * (64 * AQ * 2);
        unsigned int vst = vr_u + s * (64 * AQ * 2);
        #pragma unroll
        for (int p = 0; p < 2; p++) {
            int i = tid + p * 256;
            int r = i >> 3, q = i & 7;
            cp_async16(kst + r * (AQ * 2) + q * 16,
                       qkv + base + (long)(jt * 64 + r) * 3072 + 1024 + h * 64 + q * 8);
        }
        #pragma unroll
        for (int p = 0; p < 2; p++) {
            int i = tid + p * 256;
            int r = i >> 3, q = i & 7;
            cp_async16(vst + r * (AQ * 2) + q * 16,
                       qkv + base + (long)(jt * 64 + r) * 3072 + 2048 + h * 64 + q * 8);
        }
        asm volatile("cp.async.commit_group;\n");
    };

    issue_kv(0, 0);   // overlap first KV fetch with Q staging

    // Stage this warp's 16 Q rows into its own Ps rows, hoist fragments.
    unsigned int qa[4][4];
    {
        int r  = mrow + (lane >> 1);          // 16 rows, 2 lanes/row
        int dg = (lane & 1) * 32;
        const __half* qp = qkv + base + (long)(rowbase + r) * 3072 + h * 64 + dg;
        #pragma unroll
        for (int it = 0; it < 4; it++)
            *(uint4*)&Ps[r * AQ + dg + it * 8] = *(const uint4*)(qp + it * 8);
        __syncwarp();
        #pragma unroll
        for (int kk = 0; kk < 4; kk++)
            ldsm4(qa[kk][0], qa[kk][1], qa[kk][2], qa[kk][3],
                  ps_u + aOffP + kk * 32);
        __syncwarp();
    }

    const float sscale = 0.125f * 1.44269504f;
    float m0 = -1e30f, m1 = -1e30f, l0 = 0.f, l1 = 0.f;
    float o_[8][4];
    #pragma unroll
    for (int nt = 0; nt < 8; nt++)
        #pragma unroll
        for (int j = 0; j < 4; j++) o_[nt][j] = 0.f;

    const int row0 = rowbase + mrow + gid;
    const int row1 = row0 + 8;
    const int jmax = (rowbase >> 6) + 1;

    for (int jt = 0; jt <= jmax; jt++) {
        asm volatile("cp.async.wait_group 0;\n");
        __syncthreads();
        if (jt < jmax) issue_kv(jt + 1, (jt + 1) & 1);

        if (jt * 64 > rowbase + mrow + 15) continue;

        const unsigned int kst = kr_u + (jt & 1) * (64 * AQ * 2);
        const unsigned int vst = vr_u + (jt & 1) * (64 * AQ * 2);

        // S = Q K^T
        float s[8][4];
        #pragma unroll
        for (int nt = 0; nt < 8; nt++)
            #pragma unroll
            for (int j = 0; j < 4; j++) s[nt][j] = 0.f;

        #pragma unroll
        for (int kk = 0; kk < 4; kk++) {
            unsigned int bk[4][4];
            #pragma unroll
            for (int pr = 0; pr < 4; pr++)
                ldsm4(bk[pr][0], bk[pr][1], bk[pr][2], bk[pr][3],
                      kst + bOffK + pr * 16 * AQ * 2 + kk * 32);
            #pragma unroll
            for (int pr = 0; pr < 4; pr++) {
                mma_f16(s[pr * 2 + 0], qa[kk], bk[pr][0], bk[pr][1]);
                mma_f16(s[pr * 2 + 1], qa[kk], bk[pr][2], bk[pr][3]);
            }
        }

        const bool need_mask = (jt * 64 + 63 > rowbase + mrow);
        #pragma unroll
        for (int nt = 0; nt < 8; nt++) {
            int col = jt * 64 + nt * 8 + tig * 2;
            if (need_mask) {
                s[nt][0] = (col     <= row0) ? s[nt][0] * sscale : -1e30f;
                s[nt][1] = (col + 1 <= row0) ? s[nt][1] * sscale : -1e30f;
                s[nt][2] = (col     <= row1) ? s[nt][2] * sscale : -1e30f;
                s[nt][3] = (col + 1 <= row1) ? s[nt][3] * sscale : -1e30f;
            } else {
                s[nt][0] *= sscale; s[nt][1] *= sscale;
                s[nt][2] *= sscale; s[nt][3] *= sscale;
            }
        }

        float tm0 = -1e30f, tm1 = -1e30f;
        #pragma unroll
        for (int nt = 0; nt < 8; nt++) {
            tm0 = fmaxf(tm0, fmaxf(s[nt][0], s[nt][1]));
            tm1 = fmaxf(tm1, fmaxf(s[nt][2], s[nt][3]));
        }
        tm0 = fmaxf(tm0, __shfl_xor_sync(0xffffffffu, tm0, 1));
        tm0 = fmaxf(tm0, __shfl_xor_sync(0xffffffffu, tm0, 2));
        tm1 = fmaxf(tm1, __shfl_xor_sync(0xffffffffu, tm1, 1));
        tm1 = fmaxf(tm1, __shfl_xor_sync(0xffffffffu, tm1, 2));

        float mn0 = fmaxf(m0, tm0);
        float mn1 = fmaxf(m1, tm1);
        float corr0 = fast_exp2(m0 - mn0);
        float corr1 = fast_exp2(m1 - mn1);

        float rs0 = 0.f, rs1 = 0.f;
        #pragma unroll
        for (int nt = 0; nt < 8; nt++) {
            float p00 = fast_exp2(s[nt][0] - mn0);
            float p01 = fast_exp2(s[nt][1] - mn0);
            float p10 = fast_exp2(s[nt][2] - mn1);
            float p11 = fast_exp2(s[nt][3] - mn1);
            rs0 += p00 + p01;
            rs1 += p10 + p11;
            *(__half2*)&Ps[(mrow + gid    ) * AQ + nt * 8 + tig * 2] = __floats2half2_rn(p00, p01);
            *(__half2*)&Ps[(mrow + gid + 8) * AQ + nt * 8 + tig * 2] = __floats2half2_rn(p10, p11);
        }
        rs0 += __shfl_xor_sync(0xffffffffu, rs0, 1);
        rs0 += __shfl_xor_sync(0xffffffffu, rs0, 2);
        rs1 += __shfl_xor_sync(0xffffffffu, rs1, 1);
        rs1 += __shfl_xor_sync(0xffffffffu, rs1, 2);

        l0 = l0 * corr0 + rs0;  m0 = mn0;
        l1 = l1 * corr1 + rs1;  m1 = mn1;
        #pragma unroll
        for (int nt = 0; nt < 8; nt++) {
            o_[nt][0] *= corr0; o_[nt][1] *= corr0;
            o_[nt][2] *= corr1; o_[nt][3] *= corr1;
        }
        __syncwarp();

        // O += P V
        #pragma unroll
        for (int kk = 0; kk < 64; kk += 16) {
            unsigned int a[4], bv[4][4];
            ldsm4(a[0], a[1], a[2], a[3], ps_u + aOffP + kk * 2);
            #pragma unroll
            for (int pr = 0; pr < 4; pr++)
                ldsm4t(bv[pr][0], bv[pr][1], bv[pr][2], bv[pr][3],
                       vst + vOffB + kk * AQ * 2 + pr * 32);
            #pragma unroll
            for (int pr = 0; pr < 4; pr++) {
                mma_f16(o_[pr * 2 + 0], a, bv[pr][0], bv[pr][1]);
                mma_f16(o_[pr * 2 + 1], a, bv[pr][2], bv[pr][3]);
            }
        }
    }

    float inv0 = 1.f / l0;
    float inv1 = 1.f / l1;
    #pragma unroll
    for (int nt = 0; nt < 8; nt++) {
        int c = h * 64 + nt * 8 + tig * 2;
        *(__half2*)&obuf[(long)(b * TT + row0) * DD + c] =
            __floats2half2_rn(o_[nt][0] * inv0, o_[nt][1] * inv0);
        *(__half2*)&obuf[(long)(b * TT + row1) * DD + c] =
            __floats2half2_rn(o_[nt][2] * inv1, o_[nt][3] * inv1);
    }
}

// ---------------------------------------------------------------------------
// out = x + LayerNorm(y)*g + be ; writes f32 (outf) or half (outh).
// ---------------------------------------------------------------------------
__global__ __launch_bounds__(256) void ln_kernel(
    const float* __restrict__ x, const float* __restrict__ y,
    const float* __restrict__ g, const float* __restrict__ be,
    float* __restrict__ outf, __half* __restrict__ outh)
{
    int row = blockIdx.x;
    int tid = threadIdx.x;
    float4 v = ((const float4*)(y + (long)row * DD))[tid];
    float s  = v.x + v.y + v.z + v.w;
    float ss = v.x * v.x + v.y * v.y + v.z * v.z + v.w * v.w;
    #pragma unroll
    for (int off = 16; off >= 1; off >>= 1) {
        s  += __shfl_xor_sync(0xffffffffu, s,  off);
        ss += __shfl_xor_sync(0xffffffffu, ss, off);
    }
    __shared__ float sb[8], ssb[8];
    if ((tid & 31) == 0) { sb[tid >> 5] = s; ssb[tid >> 5] = ss; }
    __syncthreads();
    float tot = 0.f, tots = 0.f;
    #pragma unroll
    for (int w = 0; w < 8; w++) { tot += sb[w]; tots += ssb[w]; }
    float mu = tot * (1.f / 1024.f);
    float var = tots * (1.f / 1024.f) - mu * mu;
    float rstd = rsqrtf(var + 1e-5f);

    float4 xv = ((const float4*)(x + (long)row * DD))[tid];
    float4 gv = ((const float4*)g)[tid];
    float4 bv = ((const float4*)be)[tid];
    float4 o;
    o.x = xv.x + (v.x - mu) * rstd * gv.x + bv.x;
    o.y = xv.y + (v.y - mu) * rstd * gv.y + bv.y;
    o.z = xv.z + (v.z - mu) * rstd * gv.z + bv.z;
    o.w = xv.w + (v.w - mu) * rstd * gv.w + bv.w;
    if (outh) {
        __half2 h0 = __floats2half2_rn(o.x, o.y);
        __half2 h1 = __floats2half2_rn(o.z, o.w);
        *(__half2*)&outh[(long)row * DD + tid * 4]     = h0;
        *(__half2*)&outh[(long)row * DD + tid * 4 + 2] = h1;
    } else {
        ((float4*)(outf + (long)row * DD))[tid] = o;
    }
}

// ---------------------------------------------------------------------------
// launch
// ---------------------------------------------------------------------------
extern "C" void kernel_launch(void* const* d_in, const int* in_sizes, int n_in,
                              void* d_out, int out_size)
{
    const float* x   = (const float*)d_in[0];
    const float* Wq  = (const float*)d_in[1];
    const float* Wk  = (const float*)d_in[2];
    const float* Wv  = (const float*)d_in[3];
    const float* Wo  = (const float*)d_in[4];
    const float* bo  = (const float*)d_in[5];
    const float* W1  = (const float*)d_in[6];
    const float* b1  = (const float*)d_in[7];
    const float* W2  = (const float*)d_in[8];
    const float* b2  = (const float*)d_in[9];
    const float* g1  = (const float*)d_in[10];
    const float* be1 = (const float*)d_in[11];
    const float* g2  = (const float*)d_in[12];
    const float* be2 = (const float*)d_in[13];
    float* out = (float*)d_out;

    __half *packedWH, *xh, *WoH, *W1H, *W2H, *qkv, *obuf, *abuf, *h1;
    float *t1;
    cudaGetSymbolAddress((void**)&packedWH, g_packedWH);
    cudaGetSymbolAddress((void**)&xh,       g_xh);
    cudaGetSymbolAddress((void**)&WoH,      g_WoH);
    cudaGetSymbolAddress((void**)&W1H,      g_W1H);
    cudaGetSymbolAddress((void**)&W2H,      g_W2H);
    cudaGetSymbolAddress((void**)&qkv,      g_qkv);
    cudaGetSymbolAddress((void**)&obuf,     g_obuf);
    cudaGetSymbolAddress((void**)&abuf,     g_abuf);
    cudaGetSymbolAddress((void**)&h1,       g_h1);
    cudaGetSymbolAddress((void**)&t1,       g_t1);

    cudaFuncSetAttribute(attn_h_kernel,
                         cudaFuncAttributeMaxDynamicSharedMemorySize, ATTN_SMEM_BYTES);
    cudaFuncSetAttribute(hgemm_kernel,
                         cudaFuncAttributeMaxDynamicSharedMemorySize, HGEMM_SMEM);

    // 0) prep: one fused convert + QKV regroup
    convert_all_kernel<<<SEG3 / 4096, 256>>>(x, Wo, W1, W2, xh, WoH, W1H, W2H);
    convert_qkv_kernel<<<dim3(32, 48), 256>>>(Wq, Wk, Wv, packedWH);

    // 1) qkv = xh @ packedW -> half
    hgemm_kernel<<<dim3(3 * DD / 128, MROWS / 128), 256, HGEMM_SMEM>>>(
        xh, DD, packedWH, 3 * DD, DD, nullptr, qkv, 3 * DD, nullptr, 0);

    // 2) attention -> half obuf
    attn_h_kernel<<<dim3(TT / 128, HH, BB), 256, ATTN_SMEM_BYTES>>>(qkv, obuf);

    // 3) attn_out = obuf @ Wo + bo -> f32 t1
    hgemm_kernel<<<dim3(DD / 128, MROWS / 128), 256, HGEMM_SMEM>>>(
        obuf, DD, WoH, DD, DD, t1, nullptr, DD, bo, 0);

    // 4) a = x + LN(attn_out) -> half abuf
    ln_kernel<<<MROWS, 256>>>(x, t1, g1, be1, nullptr, abuf);

    // 5) h1 = relu(a @ W1 + b1) -> half
    hgemm_kernel<<<dim3(FF / 128, MROWS / 128), 256, HGEMM_SMEM>>>(
        abuf, DD, W1H, FF, DD, nullptr, h1, FF, b1, 1);

    // 6) f = h1 @ W2 + b2 -> f32 t1
    hgemm_kernel<<<dim3(DD / 128, MROWS / 128), 256, HGEMM_SMEM>>>(
        h1, FF, W2H, DD, FF, t1, nullptr, DD, b2, 0);

    // 7) out = x + LN(f)
    ln_kernel<<<MROWS, 256>>>(x, t1, g2, be2, out, nullptr);
}